// round 4
// baseline (speedup 1.0000x reference)
#include <cuda_runtime.h>
#include <cstdint>

// ---------------------------------------------------------------------------
// Problem constants
// ---------------------------------------------------------------------------
#define NXX 128
#define VOL (128*128*128)          // 2,097,152
#define NB  2
#define NR  3
#define LAMBDA 1e-3f
#define EPSI   1e-12f
#define NITER  10
#define INV128 (1.0f/128.0f)

// padded line length for smem FFT buffers (float2 elements)
#define PN 137
__device__ __forceinline__ int padi(int i){ return i + (i>>4); }

// ---------------------------------------------------------------------------
// Static device buffers (no allocations allowed).
// All CG vectors are PACKED: float2 z with z.x = batch0, z.y = batch1.
// ---------------------------------------------------------------------------
static __device__ float2 d_C0 [VOL];        // complex scratch (1 packed field)
static __device__ float2 d_tmp[NR*VOL];     // complex scratch (R packed fields)
static __device__ float  d_Se [NR*VOL];     // symmetrized SMV kernels
static __device__ uchar2 d_m8 [NR*VOL];     // masks packed (b0,b1) per radius
static __device__ float2 d_bb [VOL];
static __device__ float2 d_xk [VOL];
static __device__ float2 d_rr [VOL];
static __device__ float2 d_pp [VOL];
static __device__ float2 d_Ap [VOL];
static __device__ float2 d_W  [NXX];        // twiddle LUT e^{-2pi i k/128}
static __device__ float  d_rs [NB];
static __device__ float  d_pAp[NB];
static __device__ float  d_rsn[NB];
static __device__ float  d_part[NB*1024];

// ---------------------------------------------------------------------------
// complex helpers
// ---------------------------------------------------------------------------
__device__ __forceinline__ float2 c_add(float2 a, float2 b){ return make_float2(a.x+b.x, a.y+b.y); }
__device__ __forceinline__ float2 c_sub(float2 a, float2 b){ return make_float2(a.x-b.x, a.y-b.y); }
__device__ __forceinline__ float2 c_mul(float2 a, float2 b){ return make_float2(a.x*b.x-a.y*b.y, a.x*b.y+a.y*b.x); }

template<int DIR> __device__ __forceinline__ float2 rot90(float2 a){
  return (DIR>0) ? make_float2(a.y,-a.x) : make_float2(-a.y,a.x);
}
template<int DIR> __device__ __forceinline__ float2 twid(const float2* wt, int m){
  float2 w = wt[m];
  return (DIR>0) ? w : make_float2(w.x, -w.y);
}

template<int DIR>
__device__ __forceinline__ void dft8(float2 v[8]){
  const float C = 0.70710678118654752f;
  float2 s04a=c_add(v[0],v[4]), s04s=c_sub(v[0],v[4]);
  float2 s26a=c_add(v[2],v[6]), s26s=c_sub(v[2],v[6]);
  float2 s15a=c_add(v[1],v[5]), s15s=c_sub(v[1],v[5]);
  float2 s37a=c_add(v[3],v[7]), s37s=c_sub(v[3],v[7]);
  float2 E0=c_add(s04a,s26a), E2=c_sub(s04a,s26a);
  float2 r26=rot90<DIR>(s26s);
  float2 E1=c_add(s04s,r26), E3=c_sub(s04s,r26);
  float2 O0=c_add(s15a,s37a), O2=c_sub(s15a,s37a);
  float2 r37=rot90<DIR>(s37s);
  float2 O1=c_add(s15s,r37), O3=c_sub(s15s,r37);
  float2 w1=(DIR>0)?make_float2(C,-C):make_float2(C,C);
  float2 w3=(DIR>0)?make_float2(-C,-C):make_float2(-C,C);
  float2 t;
  v[0]=c_add(E0,O0); v[4]=c_sub(E0,O0);
  t=c_mul(O1,w1);     v[1]=c_add(E1,t); v[5]=c_sub(E1,t);
  t=rot90<DIR>(O2);   v[2]=c_add(E2,t); v[6]=c_sub(E2,t);
  t=c_mul(O3,w3);     v[3]=c_add(E3,t); v[7]=c_sub(E3,t);
}

// Stockham 128-pt FFT, radices 8,8,2. 16 lanes per line.
template<int DIR>
__device__ __forceinline__ void fft128_line(float2* bA, float2* bB, const float2* wt, int j){
  float2 v[8];
  #pragma unroll
  for (int r=0;r<8;r++) v[r] = bA[padi(j + (r<<4))];
  dft8<DIR>(v);
  #pragma unroll
  for (int r=0;r<8;r++) bB[padi((j<<3) + r)] = v[r];
  __syncthreads();
  #pragma unroll
  for (int r=0;r<8;r++) v[r] = bB[padi(j + (r<<4))];
  {
    int t8 = (j & 7) << 1;
    #pragma unroll
    for (int r=1;r<8;r++) v[r] = c_mul(v[r], twid<DIR>(wt, r*t8));
  }
  dft8<DIR>(v);
  {
    int id2 = ((j>>3)<<6) + (j&7);
    #pragma unroll
    for (int r=0;r<8;r++) bA[padi(id2 + (r<<3))] = v[r];
  }
  __syncthreads();
  #pragma unroll
  for (int k=0;k<4;k++){
    int jj = j + (k<<4);
    float2 a = bA[padi(jj)];
    float2 b = c_mul(bA[padi(jj+64)], twid<DIR>(wt, jj));
    bB[padi(jj)]    = c_add(a,b);
    bB[padi(jj+64)] = c_sub(a,b);
  }
  __syncthreads();
}

// ---------------------------------------------------------------------------
// init kernels
// ---------------------------------------------------------------------------
__global__ void k_initW(){
  int k = threadIdx.x;
  if (k < NXX){
    float s, c;
    sincospif(-(float)k/64.0f, &s, &c);
    d_W[k] = make_float2(c, s);
  }
}

// pack xk (init), wx = w3*x into d_rr (temp), masks into uchar2
__global__ __launch_bounds__(256) void k_prep(const float* __restrict__ x,
                                              const float* __restrict__ x1,
                                              const float* __restrict__ x3,
                                              const float* __restrict__ ix){
  int i = blockIdx.x*256 + threadIdx.x;
  d_xk[i] = make_float2(ix[i], ix[VOL+i]);
  d_rr[i] = make_float2(x[i]*x3[i], x[VOL+i]*x3[VOL+i]);
  #pragma unroll
  for (int r=0;r<NR;r++){
    float m0 = x1[(size_t)i*NR + r];
    float m1 = x1[(size_t)VOL*NR + (size_t)i*NR + r];
    d_m8[(size_t)r*VOL + i] = make_uchar2(m0 != 0.f, m1 != 0.f);
  }
}

// Se[r][k] = 0.5*(S[r][k] + S[r][-k])
__global__ __launch_bounds__(256) void k_prepSe(const float* __restrict__ smv){
  int r = blockIdx.y;
  int i = blockIdx.x*256 + threadIdx.x;
  int h = i >> 14, w = (i >> 7) & 127, dd = i & 127;
  int ni = (((128-h)&127) << 14) | (((128-w)&127) << 7) | ((128-dd)&127);
  d_Se[(size_t)r*VOL + i] = 0.5f*(smv[(size_t)r*VOL + i] + smv[(size_t)r*VOL + ni]);
}

// ---------------------------------------------------------------------------
// FFT pass kernels (all operate on packed complex fields)
// ---------------------------------------------------------------------------

// forward z-pass (contiguous). in: one packed field. Optional per-radius mask
// (blockIdx.y = radius). out += f*VOL.
__global__ __launch_bounds__(256) void k_fwdz(const float2* __restrict__ in,
                                              const uchar2* __restrict__ mask,
                                              float2* __restrict__ out){
  __shared__ float2 sA[16*PN], sB[16*PN], wt[NXX];
  int tid = threadIdx.x, f = blockIdx.y;
  for (int i=tid;i<NXX;i+=256) wt[i] = d_W[i];
  const uchar2* pm = mask ? (mask + (size_t)f*VOL) : (const uchar2*)0;
  size_t gbase = (size_t)blockIdx.x * 2048;
  for (int i=tid;i<2048;i+=256){
    int ln=i>>7, p=i&127;
    size_t g = gbase + (size_t)ln*128 + p;
    float2 vv = in[g];
    if (pm){ uchar2 m = pm[g]; vv.x *= (float)m.x; vv.y *= (float)m.y; }
    sA[ln*PN + padi(p)] = vv;
  }
  __syncthreads();
  int j = tid & 15, lm = tid >> 4;
  fft128_line<1>(sA + lm*PN, sB + lm*PN, wt, j);
  float2* po = out + (size_t)f*VOL;
  for (int i=tid;i<2048;i+=256){
    int ln=i>>7, p=i&127;
    po[gbase + (size_t)ln*128 + p] = sB[ln*PN + padi(p)];
  }
}

// pass along y (stride 128), complex, in-place; blockIdx.y = field
template<int DIR>
__global__ __launch_bounds__(256) void k_passy(float2* __restrict__ io, float scale){
  __shared__ float2 sA[16*PN], sB[16*PN], wt[NXX];
  int tid = threadIdx.x, f = blockIdx.y;
  for (int i=tid;i<NXX;i+=256) wt[i] = d_W[i];
  float2* p0 = io + (size_t)f*VOL;
  int l0 = blockIdx.x * 16;                 // lines over (x,z)
  size_t base = (size_t)(l0>>7)*16384 + (l0&127);
  for (int i=tid;i<2048;i+=256){
    int ln=i&15, p=i>>4;
    sA[ln*PN + padi(p)] = p0[base + ln + (size_t)p*128];
  }
  __syncthreads();
  int j = tid & 15, lm = tid >> 4;
  fft128_line<DIR>(sA + lm*PN, sB + lm*PN, wt, j);
  for (int i=tid;i<2048;i+=256){
    int ln=i&15, p=i>>4;
    float2 v = sB[ln*PN + padi(p)];
    p0[base + ln + (size_t)p*128] = make_float2(v.x*scale, v.y*scale);
  }
}

// fused: fwd-x of C0 line, then per r: *Se_r, inv-x, store tmp[r] (scale 1/128)
__global__ __launch_bounds__(128) void k_spreadx(const float2* __restrict__ cin,
                                                 const float* __restrict__ S,
                                                 float2* __restrict__ outT){
  __shared__ float2 sA[8*PN], sB[8*PN], sF[8*PN], wt[NXX];
  __shared__ float  sS[8*129];
  int tid = threadIdx.x;
  for (int i=tid;i<NXX;i+=128) wt[i] = d_W[i];
  int l0 = blockIdx.x * 8;                  // lines over (y,z)
  for (int i=tid;i<1024;i+=128){
    int ln=i&7, p=i>>3;
    sA[ln*PN + padi(p)] = cin[l0 + ln + (size_t)p*16384];
  }
  __syncthreads();
  int j = tid & 15, lm = tid >> 4;
  fft128_line<1>(sA + lm*PN, sB + lm*PN, wt, j);
  for (int i=tid;i<8*PN;i+=128) sF[i] = sB[i];
  __syncthreads();
  for (int r=0;r<NR;r++){
    for (int i=tid;i<1024;i+=128){
      int ln=i&7, p=i>>3;
      sS[ln*129+p] = S[(size_t)r*VOL + l0 + ln + (size_t)p*16384];
    }
    __syncthreads();
    for (int i=tid;i<1024;i+=128){
      int ln=i&7, p=i>>3;
      float s = sS[ln*129+p];
      float2 fv = sF[ln*PN + padi(p)];
      sA[ln*PN + padi(p)] = make_float2(fv.x*s, fv.y*s);
    }
    __syncthreads();
    fft128_line<-1>(sA + lm*PN, sB + lm*PN, wt, j);
    float2* po = outT + (size_t)r*VOL;
    for (int i=tid;i<1024;i+=128){
      int ln=i&7, p=i>>3;
      float2 v = sB[ln*PN + padi(p)];
      po[l0 + ln + (size_t)p*16384] = make_float2(v.x*INV128, v.y*INV128);
    }
    __syncthreads();
  }
}

// fused z: inv-z, *(1/128)*masks (per component/batch), fwd-z (in-place on tmp[r])
__global__ __launch_bounds__(256) void k_zfuse(float2* __restrict__ io,
                                               const uchar2* __restrict__ mask){
  __shared__ float2 sA[16*PN], sB[16*PN], wt[NXX];
  __shared__ uchar2 sM[16*129];
  int tid = threadIdx.x, f = blockIdx.y;
  for (int i=tid;i<NXX;i+=256) wt[i] = d_W[i];
  float2* p0 = io + (size_t)f*VOL;
  const uchar2* pm = mask + (size_t)f*VOL;
  size_t gbase = (size_t)blockIdx.x * 2048;
  for (int i=tid;i<2048;i+=256){
    int ln=i>>7, p=i&127;
    sA[ln*PN + padi(p)] = p0[gbase + (size_t)ln*128 + p];
    sM[ln*129 + p]      = pm[gbase + (size_t)ln*128 + p];
  }
  __syncthreads();
  int j = tid & 15, lm = tid >> 4;
  fft128_line<-1>(sA + lm*PN, sB + lm*PN, wt, j);
  for (int i=tid;i<2048;i+=256){
    int ln=i>>7, p=i&127;
    float2 v = sB[ln*PN + padi(p)];
    uchar2 m = sM[ln*129+p];
    sA[ln*PN + padi(p)] = make_float2(v.x * INV128 * (float)m.x,
                                      v.y * INV128 * (float)m.y);
  }
  __syncthreads();
  fft128_line<1>(sA + lm*PN, sB + lm*PN, wt, j);
  for (int i=tid;i<2048;i+=256){
    int ln=i>>7, p=i&127;
    p0[gbase + (size_t)ln*128 + p] = sB[ln*PN + padi(p)];
  }
}

// fused gather: for r: fwd-x(tmp[r]) * Se_r, sum; inv-x; store C0 (scale 1/128)
__global__ __launch_bounds__(128) void k_gatherx(const float2* __restrict__ tmp,
                                                 const float* __restrict__ S,
                                                 float2* __restrict__ cout){
  __shared__ float2 sA[8*PN], sB[8*PN], sF[8*PN], wt[NXX];
  __shared__ float  sS[8*129];
  int tid = threadIdx.x;
  for (int i=tid;i<NXX;i+=128) wt[i] = d_W[i];
  int l0 = blockIdx.x * 8;
  for (int i=tid;i<8*PN;i+=128) sF[i] = make_float2(0.f,0.f);
  int j = tid & 15, lm = tid >> 4;
  for (int r=0;r<NR;r++){
    const float2* pin = tmp + (size_t)r*VOL;
    for (int i=tid;i<1024;i+=128){
      int ln=i&7, p=i>>3;
      sA[ln*PN + padi(p)] = pin[l0 + ln + (size_t)p*16384];
    }
    __syncthreads();
    fft128_line<1>(sA + lm*PN, sB + lm*PN, wt, j);
    for (int i=tid;i<1024;i+=128){
      int ln=i&7, p=i>>3;
      sS[ln*129+p] = S[(size_t)r*VOL + l0 + ln + (size_t)p*16384];
    }
    __syncthreads();
    for (int i=tid;i<1024;i+=128){
      int ln=i&7, p=i>>3;
      float s = sS[ln*129+p];
      float2 v = sB[ln*PN + padi(p)];
      float2 f = sF[ln*PN + padi(p)];
      sF[ln*PN + padi(p)] = make_float2(f.x + v.x*s, f.y + v.y*s);
    }
    __syncthreads();
  }
  for (int i=tid;i<8*PN;i+=128) sA[i] = sF[i];
  __syncthreads();
  fft128_line<-1>(sA + lm*PN, sB + lm*PN, wt, j);
  for (int i=tid;i<1024;i+=128){
    int ln=i&7, p=i>>3;
    float2 v = sB[l0 >= 0 ? (lm*0 + (i&7)*PN + padi(i>>3)) : 0];  // (placeholder removed below)
    (void)v;
    float2 vv = sB[(i&7)*PN + padi(i>>3)];
    cout[l0 + (i&7) + (size_t)(i>>3)*16384] = make_float2(vv.x*INV128, vv.y*INV128);
  }
}

// inv-z + Ap = re/im*(1/128) + lam*p, fused partial dot(p,Ap) per batch
__global__ __launch_bounds__(256) void k_invz_ap(const float2* __restrict__ cin,
                                                 float2* __restrict__ outAp,
                                                 const float2* __restrict__ pvec,
                                                 float lam,
                                                 float* __restrict__ part){
  __shared__ float2 sA[16*PN], sB[16*PN], wt[NXX];
  __shared__ float sm0[256], sm1[256];
  int tid = threadIdx.x;
  for (int i=tid;i<NXX;i+=256) wt[i] = d_W[i];
  size_t gbase = (size_t)blockIdx.x * 2048;
  for (int i=tid;i<2048;i+=256){
    int ln=i>>7, p=i&127;
    sA[ln*PN + padi(p)] = cin[gbase + (size_t)ln*128 + p];
  }
  __syncthreads();
  int j = tid & 15, lm = tid >> 4;
  fft128_line<-1>(sA + lm*PN, sB + lm*PN, wt, j);
  float s0 = 0.f, s1 = 0.f;
  for (int i=tid;i<2048;i+=256){
    int ln=i>>7, p=i&127;
    size_t g = gbase + (size_t)ln*128 + p;
    float2 v = sB[ln*PN + padi(p)];
    float2 ap = make_float2(v.x*INV128, v.y*INV128);
    if (pvec){
      float2 pv = pvec[g];
      ap.x += lam*pv.x; ap.y += lam*pv.y;
      s0 += pv.x*ap.x;  s1 += pv.y*ap.y;
    }
    outAp[g] = ap;
  }
  if (part){
    sm0[tid]=s0; sm1[tid]=s1; __syncthreads();
    for (int s=128;s>0;s>>=1){ if (tid<s){ sm0[tid]+=sm0[tid+s]; sm1[tid]+=sm1[tid+s]; } __syncthreads(); }
    if (tid==0){ part[blockIdx.x]=sm0[0]; part[1024+blockIdx.x]=sm1[0]; }
  }
}

// ---------------------------------------------------------------------------
// CG scalar machinery (deterministic two-stage reductions, packed)
// ---------------------------------------------------------------------------
__global__ void k_fin(const float* __restrict__ part, float* __restrict__ out, int n){
  __shared__ float sm[256];
  int b = blockIdx.x, t = threadIdx.x;
  float s = 0.f;
  for (int jj=t; jj<n; jj+=256) s += part[b*1024 + jj];
  sm[t]=s; __syncthreads();
  for (int st=128; st>0; st>>=1){ if (t<st) sm[t]+=sm[t+st]; __syncthreads(); }
  if (t==0) out[b] = sm[0];
}

__global__ __launch_bounds__(256) void k_init_r(float* __restrict__ part){
  __shared__ float sm0[256], sm1[256];
  int t = threadIdx.x;
  float s0=0.f, s1=0.f;
  for (int i=blockIdx.x*256+t; i<VOL; i+=256*256){
    float2 v = make_float2(d_bb[i].x - d_Ap[i].x, d_bb[i].y - d_Ap[i].y);
    d_rr[i]=v; d_pp[i]=v;
    s0 += v.x*v.x; s1 += v.y*v.y;
  }
  sm0[t]=s0; sm1[t]=s1; __syncthreads();
  for (int st=128; st>0; st>>=1){ if (t<st){ sm0[t]+=sm0[t+st]; sm1[t]+=sm1[t+st]; } __syncthreads(); }
  if (t==0){ part[blockIdx.x]=sm0[0]; part[1024+blockIdx.x]=sm1[0]; }
}

__global__ __launch_bounds__(256) void k_update1(float* __restrict__ part){
  __shared__ float sm0[256], sm1[256];
  int t = threadIdx.x;
  float a0 = d_rs[0] / (d_pAp[0] + EPSI);
  float a1 = d_rs[1] / (d_pAp[1] + EPSI);
  float s0=0.f, s1=0.f;
  for (int i=blockIdx.x*256+t; i<VOL; i+=256*256){
    float2 p = d_pp[i], ap = d_Ap[i], xk = d_xk[i], r = d_rr[i];
    xk.x += a0*p.x;  xk.y += a1*p.y;  d_xk[i]=xk;
    r.x  -= a0*ap.x; r.y  -= a1*ap.y; d_rr[i]=r;
    s0 += r.x*r.x;   s1 += r.y*r.y;
  }
  sm0[t]=s0; sm1[t]=s1; __syncthreads();
  for (int st=128; st>0; st>>=1){ if (t<st){ sm0[t]+=sm0[t+st]; sm1[t]+=sm1[t+st]; } __syncthreads(); }
  if (t==0){ part[blockIdx.x]=sm0[0]; part[1024+blockIdx.x]=sm1[0]; }
}

__global__ __launch_bounds__(256) void k_update2(){
  float b0 = d_rsn[0] / (d_rs[0] + EPSI);
  float b1 = d_rsn[1] / (d_rs[1] + EPSI);
  for (int i=blockIdx.x*256+threadIdx.x; i<VOL; i+=256*256){
    float2 r = d_rr[i], p = d_pp[i];
    d_pp[i] = make_float2(r.x + b0*p.x, r.y + b1*p.y);
  }
}

__global__ void k_rscopy(){
  if (threadIdx.x < NB) d_rs[threadIdx.x] = d_rsn[threadIdx.x];
}

__global__ __launch_bounds__(256) void k_unpack(float* __restrict__ out){
  int i = blockIdx.x*256 + threadIdx.x;
  float2 v = d_xk[i];
  out[i] = v.x;
  out[VOL+i] = v.y;
}

// ---------------------------------------------------------------------------
// Host side
// ---------------------------------------------------------------------------
static void applyA(const float2* vin, float2* vout, float* pPart,
                   float2* pC0, float2* pTmp, const float* pSe, const uchar2* pM8){
  k_fwdz   <<<dim3(1024,1), 256>>>(vin, 0, pC0);
  k_passy<1><<<dim3(1024,1), 256>>>(pC0, 1.f);
  k_spreadx<<<2048, 128>>>(pC0, pSe, pTmp);
  k_passy<-1><<<dim3(1024,NR), 256>>>(pTmp, INV128);
  k_zfuse  <<<dim3(1024,NR), 256>>>(pTmp, pM8);
  k_passy<1><<<dim3(1024,NR), 256>>>(pTmp, 1.f);
  k_gatherx<<<2048, 128>>>(pTmp, pSe, pC0);
  k_passy<-1><<<dim3(1024,1), 256>>>(pC0, INV128);
  k_invz_ap<<<dim3(1024,1), 256>>>(pC0, vout, vin, LAMBDA, pPart);
}

extern "C" void kernel_launch(void* const* d_in, const int* in_sizes, int n_in,
                              void* d_out, int out_size){
  const float* x      = (const float*)d_in[0];   // [B,V]
  const float* x1     = (const float*)d_in[1];   // [B,V,R]
  const float* x3     = (const float*)d_in[2];   // [B,V]
  const float* init_x = (const float*)d_in[3];   // [B,V]
  const float* smv    = (const float*)d_in[4];   // [R,V]
  float* out = (float*)d_out;

  float2 *pC0, *pTmp, *pB, *pXk, *pR, *pP, *pAp;
  float *pSe, *pRs, *pPAp, *pRsn, *pPart;
  uchar2 *pM8;
  cudaGetSymbolAddress((void**)&pC0,  d_C0);
  cudaGetSymbolAddress((void**)&pTmp, d_tmp);
  cudaGetSymbolAddress((void**)&pSe,  d_Se);
  cudaGetSymbolAddress((void**)&pM8,  d_m8);
  cudaGetSymbolAddress((void**)&pB,   d_bb);
  cudaGetSymbolAddress((void**)&pXk,  d_xk);
  cudaGetSymbolAddress((void**)&pR,   d_rr);
  cudaGetSymbolAddress((void**)&pP,   d_pp);
  cudaGetSymbolAddress((void**)&pAp,  d_Ap);
  cudaGetSymbolAddress((void**)&pRs,  d_rs);
  cudaGetSymbolAddress((void**)&pPAp, d_pAp);
  cudaGetSymbolAddress((void**)&pRsn, d_rsn);
  cudaGetSymbolAddress((void**)&pPart,d_part);

  k_initW <<<1,128>>>();
  k_prep  <<<VOL/256, 256>>>(x, x1, x3, init_x);
  k_prepSe<<<dim3(VOL/256, NR), 256>>>(smv);

  // b = smv_adj( m * (w3 * x) )   -- wx packed is sitting in d_rr
  k_fwdz   <<<dim3(1024,NR), 256>>>(pR, pM8, pTmp);
  k_passy<1><<<dim3(1024,NR), 256>>>(pTmp, 1.f);
  k_gatherx<<<2048, 128>>>(pTmp, pSe, pC0);
  k_passy<-1><<<dim3(1024,1), 256>>>(pC0, INV128);
  k_invz_ap<<<dim3(1024,1), 256>>>(pC0, pB, 0, 0.f, 0);

  // r0 = b - A(x0); p = r0; rs = <r0,r0>
  applyA(pXk, pAp, 0, pC0, pTmp, pSe, pM8);
  k_init_r<<<256, 256>>>(pPart);
  k_fin<<<NB, 256>>>(pPart, pRs, 256);

  for (int it=0; it<NITER; ++it){
    applyA(pP, pAp, pPart, pC0, pTmp, pSe, pM8);
    k_fin<<<NB, 256>>>(pPart, pPAp, 1024);
    k_update1<<<256, 256>>>(pPart);
    k_fin<<<NB, 256>>>(pPart, pRsn, 256);
    k_update2<<<256, 256>>>();
    k_rscopy<<<1, 32>>>();
  }

  k_unpack<<<VOL/256, 256>>>(out);
}

// round 5
// speedup vs baseline: 1.1596x; 1.1596x over previous
#include <cuda_runtime.h>
#include <cstdint>

#define NXX 128
#define VOL (128*128*128)
#define NB  2
#define NR  3
#define LAMBDA 1e-3f
#define EPSI   1e-12f
#define NITER  10
#define INV128f 0.0078125f
#define PLANE_SMEM 133120   // (2*16512 + 256) floats * 4 bytes

// ---------------------------------------------------------------------------
// Buffers. CG vectors packed float2 (x=batch0, y=batch1), natural [x][y][z].
// C0/tmp transposed [zp][x][y] (y contig). Se permuted [zp][yp][xp].
// ---------------------------------------------------------------------------
static __device__ float2 d_C0 [VOL];
static __device__ float2 d_tmp[NR*VOL];
static __device__ float  d_Se [NR*VOL];
static __device__ uchar2 d_m8 [NR*VOL];
static __device__ float2 d_bb [VOL];
static __device__ float2 d_xk [VOL];
static __device__ float2 d_rr [VOL];
static __device__ float2 d_pp [VOL];
static __device__ float2 d_Ap [VOL];
static __device__ float2 d_W  [NXX];
static __device__ float  d_rs [NB];
static __device__ float  d_pAp[NB];
static __device__ float  d_rsn[NB];
static __device__ float  d_part[NB*1024];

__device__ __forceinline__ float2 c_add(float2 a, float2 b){ return make_float2(a.x+b.x, a.y+b.y); }
__device__ __forceinline__ float2 c_sub(float2 a, float2 b){ return make_float2(a.x-b.x, a.y-b.y); }
__device__ __forceinline__ float2 c_mul(float2 a, float2 b){ return make_float2(a.x*b.x-a.y*b.y, a.x*b.y+a.y*b.x); }
__device__ __forceinline__ float2 conjf2(float2 a){ return make_float2(a.x, -a.y); }

// ---------------------------------------------------------------------------
// Warp 128-pt FFT. Lane l, reg k holds x[l+32k] (forward input, natural).
// Forward output: memory position p = l + 32*k0 holds X[k(p)],
// k(p) = (p>>5) + 4*bitrev5(p&31). Inverse consumes that layout, returns
// natural order scaled by 1/128.
// ---------------------------------------------------------------------------
template<int INV>
__device__ __forceinline__ void wfft128(float2 v[4], const float2* __restrict__ sW, int l){
  if (!INV){
    float2 t0=c_add(v[0],v[2]), t1=c_sub(v[0],v[2]);
    float2 t2=c_add(v[1],v[3]), t3=c_sub(v[1],v[3]);
    float2 mi3 = make_float2(t3.y, -t3.x);
    v[0]=c_add(t0,t2); v[2]=c_sub(t0,t2);
    v[1]=c_add(t1,mi3); v[3]=c_sub(t1,mi3);
    v[1]=c_mul(v[1], sW[l]);
    v[2]=c_mul(v[2], sW[2*l]);
    v[3]=c_mul(v[3], sW[3*l]);
    #pragma unroll
    for (int d=16; d>=1; d>>=1){
      int e = (l & (d-1)) * (64/d);
      float2 w = sW[e];
      bool up = (l & d) != 0;
      #pragma unroll
      for (int k=0;k<4;k++){
        float2 p;
        p.x = __shfl_xor_sync(0xffffffffu, v[k].x, d);
        p.y = __shfl_xor_sync(0xffffffffu, v[k].y, d);
        v[k] = up ? c_mul(c_sub(p, v[k]), w) : c_add(v[k], p);
      }
    }
  } else {
    #pragma unroll
    for (int d=1; d<=16; d<<=1){
      int e = (l & (d-1)) * (64/d);
      float2 w = conjf2(sW[e]);
      bool up = (l & d) != 0;
      #pragma unroll
      for (int k=0;k<4;k++){
        float2 own = up ? c_mul(v[k], w) : v[k];
        float2 p;
        p.x = __shfl_xor_sync(0xffffffffu, own.x, d);
        p.y = __shfl_xor_sync(0xffffffffu, own.y, d);
        v[k] = up ? c_sub(p, own) : c_add(own, p);
      }
    }
    float2 w1 = conjf2(sW[l]), w2 = conjf2(sW[2*l]), w3 = conjf2(sW[3*l]);
    v[0] = make_float2(v[0].x*INV128f, v[0].y*INV128f);
    v[1] = c_mul(v[1], make_float2(w1.x*INV128f, w1.y*INV128f));
    v[2] = c_mul(v[2], make_float2(w2.x*INV128f, w2.y*INV128f));
    v[3] = c_mul(v[3], make_float2(w3.x*INV128f, w3.y*INV128f));
    float2 t0=c_add(v[0],v[2]), t1=c_sub(v[0],v[2]);
    float2 t2=c_add(v[1],v[3]), t3=c_sub(v[1],v[3]);
    float2 pi3 = make_float2(-t3.y, t3.x);
    v[0]=c_add(t0,t2); v[2]=c_sub(t0,t2);
    v[1]=c_add(t1,pi3); v[3]=c_sub(t1,pi3);
  }
}

// ---------------------------------------------------------------------------
// init kernels
// ---------------------------------------------------------------------------
__global__ void k_initW(){
  int k = threadIdx.x;
  if (k < NXX){
    float s, c;
    sincospif(-(float)k/64.0f, &s, &c);
    d_W[k] = make_float2(c, s);
  }
}

__global__ __launch_bounds__(256) void k_prep(const float* __restrict__ x,
                                              const float* __restrict__ x1,
                                              const float* __restrict__ x3,
                                              const float* __restrict__ ix){
  int i = blockIdx.x*256 + threadIdx.x;
  d_xk[i] = make_float2(ix[i], ix[VOL+i]);
  d_rr[i] = make_float2(x[i]*x3[i], x[VOL+i]*x3[VOL+i]);
  #pragma unroll
  for (int r=0;r<NR;r++){
    float m0 = x1[(size_t)i*NR + r];
    float m1 = x1[(size_t)VOL*NR + (size_t)i*NR + r];
    d_m8[(size_t)r*VOL + i] = make_uchar2(m0 != 0.f, m1 != 0.f);
  }
}

__device__ __forceinline__ int kofp(int p){
  int l = p & 31, k2 = p >> 5;
  return k2 + 4*(int)(__brev((unsigned)l) >> 27);
}

// Se_perm[zp][yp][xp] = 0.5*(smv[k(xp),k(yp),k(zp)] + smv[-k...])
__global__ __launch_bounds__(256) void k_prepSe(const float* __restrict__ smv){
  int r = blockIdx.y;
  int o = blockIdx.x*256 + threadIdx.x;
  int zp = o>>14, yp = (o>>7)&127, xp = o&127;
  int kx = kofp(xp), ky = kofp(yp), kz = kofp(zp);
  int i1 = (kx<<14) | (ky<<7) | kz;
  int i2 = (((128-kx)&127)<<14) | (((128-ky)&127)<<7) | ((128-kz)&127);
  d_Se[(size_t)r*VOL + o] = 0.5f*(smv[(size_t)r*VOL + i1] + smv[(size_t)r*VOL + i2]);
}

// ---------------------------------------------------------------------------
// fwd-z with transpose-out: in natural [x][y][z] -> out[f][zp][x][y].
// Optional spatial mask per radius f; optional fused p = r + beta*p update.
// ---------------------------------------------------------------------------
__global__ __launch_bounds__(256) void k_fwdzT(const float2* __restrict__ in,
                                               const uchar2* __restrict__ mask,
                                               float2* __restrict__ out,
                                               int betaFlag,
                                               const float2* __restrict__ rvec,
                                               float2* __restrict__ pwrite){
  __shared__ float tR[128*33], tI[128*33];
  __shared__ float2 sW[NXX];
  int tid=threadIdx.x, l=tid&31, w=tid>>5;
  int x=blockIdx.x, yt=blockIdx.y, f=blockIdx.z;
  for (int i=tid;i<NXX;i+=256) sW[i]=d_W[i];
  __syncthreads();
  float b0=0.f, b1=0.f;
  if (betaFlag){ b0 = d_rsn[0]/(d_rs[0]+EPSI); b1 = d_rsn[1]/(d_rs[1]+EPSI); }
  const uchar2* pm = mask ? (mask + (size_t)f*VOL) : (const uchar2*)0;
  for (int ln=0; ln<4; ln++){
    int c=(w<<2)+ln;
    int y=(yt<<5)+c;
    size_t base=(size_t)x*16384 + (size_t)y*128;
    float2 v[4];
    #pragma unroll
    for (int k=0;k<4;k++){
      int z=l+(k<<5);
      float2 t=in[base+z];
      if (betaFlag){
        float2 rv=rvec[base+z];
        t=make_float2(rv.x+b0*t.x, rv.y+b1*t.y);
        pwrite[base+z]=t;
      }
      if (pm){ uchar2 m=pm[base+z]; t.x*=(float)m.x; t.y*=(float)m.y; }
      v[k]=t;
    }
    wfft128<0>(v,sW,l);
    #pragma unroll
    for (int k=0;k<4;k++){ int p=l+(k<<5); tR[p*33+c]=v[k].x; tI[p*33+c]=v[k].y; }
  }
  __syncthreads();
  float2* po = out + (size_t)f*VOL + (size_t)x*128 + ((size_t)yt<<5);
  for (int i=tid;i<4096;i+=256){
    int zp=i>>5, c=i&31;
    po[(size_t)zp*16384 + c] = make_float2(tR[zp*33+c], tI[zp*33+c]);
  }
}

// ---------------------------------------------------------------------------
// plane spread: per zp: fwd-y, fwd-x (F in regs), per r: *Se_r, inv-x, inv-y,
// store tmp[r][zp][x][y].
// ---------------------------------------------------------------------------
__global__ __launch_bounds__(512,1) void k_plane1(const float2* __restrict__ cin,
                                                  const float* __restrict__ Se,
                                                  float2* __restrict__ outT){
  extern __shared__ float ps[];
  float* pR=ps; float* pI=ps+16512; float2* sW=(float2*)(ps+33024);
  int tid=threadIdx.x, l=tid&31, w=tid>>5;   // 16 warps
  int zp=blockIdx.x;
  for (int i=tid;i<NXX;i+=512) sW[i]=d_W[i];
  const float2* pin = cin + (size_t)zp*16384;
  for (int i=tid;i<16384;i+=512){
    float2 t=pin[i];
    pR[(i>>7)*129+(i&127)]=t.x; pI[(i>>7)*129+(i&127)]=t.y;
  }
  __syncthreads();
  float2 v[4];
  for (int ln=0; ln<8; ln++){                 // fwd-y (rows = fixed x)
    int rb=((w<<3)+ln)*129;
    #pragma unroll
    for (int k=0;k<4;k++){ int y=l+(k<<5); v[k]=make_float2(pR[rb+y],pI[rb+y]); }
    wfft128<0>(v,sW,l);
    #pragma unroll
    for (int k=0;k<4;k++){ int y=l+(k<<5); pR[rb+y]=v[k].x; pI[rb+y]=v[k].y; }
  }
  __syncthreads();
  float2 F[8][4];
  for (int ln=0; ln<8; ln++){                 // fwd-x (cols = fixed y), keep F
    int yc=(w<<3)+ln;
    #pragma unroll
    for (int k=0;k<4;k++){ int xi=l+(k<<5); F[ln][k]=make_float2(pR[xi*129+yc],pI[xi*129+yc]); }
    wfft128<0>(F[ln],sW,l);
  }
  for (int r=0;r<NR;r++){
    __syncthreads();
    const float* pS = Se + (size_t)r*VOL + (size_t)zp*16384;
    for (int ln=0; ln<8; ln++){
      int yc=(w<<3)+ln;
      #pragma unroll
      for (int k=0;k<4;k++){
        float s=pS[yc*128 + l+(k<<5)];
        v[k]=make_float2(F[ln][k].x*s, F[ln][k].y*s);
      }
      wfft128<1>(v,sW,l);
      #pragma unroll
      for (int k=0;k<4;k++){ int xi=l+(k<<5); pR[xi*129+yc]=v[k].x; pI[xi*129+yc]=v[k].y; }
    }
    __syncthreads();
    for (int ln=0; ln<8; ln++){
      int rb=((w<<3)+ln)*129;
      #pragma unroll
      for (int k=0;k<4;k++){ int y=l+(k<<5); v[k]=make_float2(pR[rb+y],pI[rb+y]); }
      wfft128<1>(v,sW,l);
      #pragma unroll
      for (int k=0;k<4;k++){ int y=l+(k<<5); pR[rb+y]=v[k].x; pI[rb+y]=v[k].y; }
    }
    __syncthreads();
    float2* po = outT + (size_t)r*VOL + (size_t)zp*16384;
    for (int i=tid;i<16384;i+=512)
      po[i]=make_float2(pR[(i>>7)*129+(i&127)], pI[(i>>7)*129+(i&127)]);
  }
}

// ---------------------------------------------------------------------------
// fused z on tmp[r]: inv-z, spatial mask, fwd-z (in-place, transposed layout).
// ---------------------------------------------------------------------------
__global__ __launch_bounds__(256) void k_zfuseT(float2* __restrict__ io,
                                                const uchar2* __restrict__ mask){
  __shared__ float tR[128*33], tI[128*33];
  __shared__ float2 sW[NXX];
  int tid=threadIdx.x, l=tid&31, w=tid>>5;
  int x=blockIdx.x, yt=blockIdx.y, f=blockIdx.z;
  for (int i=tid;i<NXX;i+=256) sW[i]=d_W[i];
  float2* p0 = io + (size_t)f*VOL + (size_t)x*128 + ((size_t)yt<<5);
  for (int i=tid;i<4096;i+=256){
    int zp=i>>5, c=i&31;
    float2 t = p0[(size_t)zp*16384 + c];
    tR[zp*33+c]=t.x; tI[zp*33+c]=t.y;
  }
  __syncthreads();
  const uchar2* pm = mask + (size_t)f*VOL;
  for (int ln=0; ln<4; ln++){
    int c=(w<<2)+ln;
    int y=(yt<<5)+c;
    float2 v[4];
    #pragma unroll
    for (int k=0;k<4;k++){ int p=l+(k<<5); v[k]=make_float2(tR[p*33+c], tI[p*33+c]); }
    wfft128<1>(v,sW,l);
    size_t base=(size_t)x*16384 + (size_t)y*128;
    #pragma unroll
    for (int k=0;k<4;k++){
      int z=l+(k<<5);
      uchar2 m=pm[base+z];
      v[k].x*=(float)m.x; v[k].y*=(float)m.y;
    }
    wfft128<0>(v,sW,l);
    #pragma unroll
    for (int k=0;k<4;k++){ int p=l+(k<<5); tR[p*33+c]=v[k].x; tI[p*33+c]=v[k].y; }
  }
  __syncthreads();
  for (int i=tid;i<4096;i+=256){
    int zp=i>>5, c=i&31;
    p0[(size_t)zp*16384 + c] = make_float2(tR[zp*33+c], tI[zp*33+c]);
  }
}

// ---------------------------------------------------------------------------
// plane gather: per zp: for r: fwd-y, fwd-x, acc += Se_r*(.), then inv-x,
// inv-y, store C0[zp][x][y].
// ---------------------------------------------------------------------------
__global__ __launch_bounds__(512,1) void k_plane2(const float2* __restrict__ tmp,
                                                  const float* __restrict__ Se,
                                                  float2* __restrict__ cout){
  extern __shared__ float ps[];
  float* pR=ps; float* pI=ps+16512; float2* sW=(float2*)(ps+33024);
  int tid=threadIdx.x, l=tid&31, w=tid>>5;
  int zp=blockIdx.x;
  for (int i=tid;i<NXX;i+=512) sW[i]=d_W[i];
  float2 acc[8][4];
  #pragma unroll
  for (int a=0;a<8;a++)
    #pragma unroll
    for (int k=0;k<4;k++) acc[a][k]=make_float2(0.f,0.f);
  float2 v[4];
  for (int r=0;r<NR;r++){
    const float2* pin = tmp + (size_t)r*VOL + (size_t)zp*16384;
    __syncthreads();
    for (int i=tid;i<16384;i+=512){
      float2 t=pin[i];
      pR[(i>>7)*129+(i&127)]=t.x; pI[(i>>7)*129+(i&127)]=t.y;
    }
    __syncthreads();
    for (int ln=0; ln<8; ln++){               // fwd-y
      int rb=((w<<3)+ln)*129;
      #pragma unroll
      for (int k=0;k<4;k++){ int y=l+(k<<5); v[k]=make_float2(pR[rb+y],pI[rb+y]); }
      wfft128<0>(v,sW,l);
      #pragma unroll
      for (int k=0;k<4;k++){ int y=l+(k<<5); pR[rb+y]=v[k].x; pI[rb+y]=v[k].y; }
    }
    __syncthreads();
    const float* pS = Se + (size_t)r*VOL + (size_t)zp*16384;
    for (int ln=0; ln<8; ln++){               // fwd-x + accumulate
      int yc=(w<<3)+ln;
      #pragma unroll
      for (int k=0;k<4;k++){ int xi=l+(k<<5); v[k]=make_float2(pR[xi*129+yc],pI[xi*129+yc]); }
      wfft128<0>(v,sW,l);
      #pragma unroll
      for (int k=0;k<4;k++){
        float s=pS[yc*128 + l+(k<<5)];
        acc[ln][k].x += v[k].x*s; acc[ln][k].y += v[k].y*s;
      }
    }
  }
  __syncthreads();
  for (int ln=0; ln<8; ln++){                 // inv-x from acc
    int yc=(w<<3)+ln;
    #pragma unroll
    for (int k=0;k<4;k++) v[k]=acc[ln][k];
    wfft128<1>(v,sW,l);
    #pragma unroll
    for (int k=0;k<4;k++){ int xi=l+(k<<5); pR[xi*129+yc]=v[k].x; pI[xi*129+yc]=v[k].y; }
  }
  __syncthreads();
  for (int ln=0; ln<8; ln++){                 // inv-y
    int rb=((w<<3)+ln)*129;
    #pragma unroll
    for (int k=0;k<4;k++){ int y=l+(k<<5); v[k]=make_float2(pR[rb+y],pI[rb+y]); }
    wfft128<1>(v,sW,l);
    #pragma unroll
    for (int k=0;k<4;k++){ int y=l+(k<<5); pR[rb+y]=v[k].x; pI[rb+y]=v[k].y; }
  }
  __syncthreads();
  float2* po = cout + (size_t)zp*16384;
  for (int i=tid;i<16384;i+=512)
    po[i]=make_float2(pR[(i>>7)*129+(i&127)], pI[(i>>7)*129+(i&127)]);
}

// ---------------------------------------------------------------------------
// inv-z from transposed -> natural Ap = (.) + lam*p, fused partial dot(p,Ap)
// ---------------------------------------------------------------------------
__global__ __launch_bounds__(256) void k_invzT_ap(const float2* __restrict__ cin,
                                                  float2* __restrict__ outAp,
                                                  const float2* __restrict__ pvec,
                                                  float lam, float* __restrict__ part){
  __shared__ float tR[128*33], tI[128*33];
  __shared__ float2 sW[NXX];
  __shared__ float sm0[256], sm1[256];
  int tid=threadIdx.x, l=tid&31, w=tid>>5;
  int x=blockIdx.x, yt=blockIdx.y;
  for (int i=tid;i<NXX;i+=256) sW[i]=d_W[i];
  const float2* p0 = cin + (size_t)x*128 + ((size_t)yt<<5);
  for (int i=tid;i<4096;i+=256){
    int zp=i>>5, c=i&31;
    float2 t = p0[(size_t)zp*16384 + c];
    tR[zp*33+c]=t.x; tI[zp*33+c]=t.y;
  }
  __syncthreads();
  float s0=0.f, s1=0.f;
  for (int ln=0; ln<4; ln++){
    int c=(w<<2)+ln, y=(yt<<5)+c;
    float2 v[4];
    #pragma unroll
    for (int k=0;k<4;k++){ int p=l+(k<<5); v[k]=make_float2(tR[p*33+c], tI[p*33+c]); }
    wfft128<1>(v,sW,l);
    size_t base=(size_t)x*16384 + (size_t)y*128;
    #pragma unroll
    for (int k=0;k<4;k++){
      int z=l+(k<<5);
      float2 ap=v[k];
      if (pvec){
        float2 pv=pvec[base+z];
        ap.x+=lam*pv.x; ap.y+=lam*pv.y;
        s0+=pv.x*ap.x; s1+=pv.y*ap.y;
      }
      outAp[base+z]=ap;
    }
  }
  if (part){
    sm0[tid]=s0; sm1[tid]=s1; __syncthreads();
    for (int s=128;s>0;s>>=1){ if(tid<s){sm0[tid]+=sm0[tid+s];sm1[tid]+=sm1[tid+s];} __syncthreads(); }
    if (tid==0){ int b=blockIdx.x*4+blockIdx.y; part[b]=sm0[0]; part[1024+b]=sm1[0]; }
  }
}

// ---------------------------------------------------------------------------
// CG scalar machinery
// ---------------------------------------------------------------------------
__global__ void k_fin(const float* __restrict__ part, float* __restrict__ out, int n){
  __shared__ float sm[256];
  int b = blockIdx.x, t = threadIdx.x;
  float s = 0.f;
  for (int jj=t; jj<n; jj+=256) s += part[b*1024 + jj];
  sm[t]=s; __syncthreads();
  for (int st=128; st>0; st>>=1){ if (t<st) sm[t]+=sm[t+st]; __syncthreads(); }
  if (t==0) out[b] = sm[0];
}

__global__ __launch_bounds__(256) void k_init_r(float* __restrict__ part){
  __shared__ float sm0[256], sm1[256];
  int t = threadIdx.x;
  float s0=0.f, s1=0.f;
  for (int i=blockIdx.x*256+t; i<VOL; i+=256*256){
    float2 v = make_float2(d_bb[i].x - d_Ap[i].x, d_bb[i].y - d_Ap[i].y);
    d_rr[i]=v; d_pp[i]=v;
    s0 += v.x*v.x; s1 += v.y*v.y;
  }
  sm0[t]=s0; sm1[t]=s1; __syncthreads();
  for (int st=128; st>0; st>>=1){ if (t<st){ sm0[t]+=sm0[t+st]; sm1[t]+=sm1[t+st]; } __syncthreads(); }
  if (t==0){ part[blockIdx.x]=sm0[0]; part[1024+blockIdx.x]=sm1[0]; }
}

__global__ __launch_bounds__(256) void k_update1(float* __restrict__ part){
  __shared__ float sm0[256], sm1[256];
  int t = threadIdx.x;
  float a0 = d_rs[0] / (d_pAp[0] + EPSI);
  float a1 = d_rs[1] / (d_pAp[1] + EPSI);
  float s0=0.f, s1=0.f;
  for (int i=blockIdx.x*256+t; i<VOL; i+=256*256){
    float2 p = d_pp[i], ap = d_Ap[i], xk = d_xk[i], r = d_rr[i];
    xk.x += a0*p.x;  xk.y += a1*p.y;  d_xk[i]=xk;
    r.x  -= a0*ap.x; r.y  -= a1*ap.y; d_rr[i]=r;
    s0 += r.x*r.x;   s1 += r.y*r.y;
  }
  sm0[t]=s0; sm1[t]=s1; __syncthreads();
  for (int st=128; st>0; st>>=1){ if (t<st){ sm0[t]+=sm0[t+st]; sm1[t]+=sm1[t+st]; } __syncthreads(); }
  if (t==0){ part[blockIdx.x]=sm0[0]; part[1024+blockIdx.x]=sm1[0]; }
}

__global__ void k_rscopy(){
  if (threadIdx.x < NB) d_rs[threadIdx.x] = d_rsn[threadIdx.x];
}

__global__ __launch_bounds__(256) void k_unpack(float* __restrict__ out){
  int i = blockIdx.x*256 + threadIdx.x;
  float2 v = d_xk[i];
  out[i] = v.x;
  out[VOL+i] = v.y;
}

// ---------------------------------------------------------------------------
// Host side
// ---------------------------------------------------------------------------
static void applyA(const float2* vin, float2* vout, float* pPart, int beta,
                   float2* pC0, float2* pTmp, const float* pSe, const uchar2* pM8,
                   float2* pR, float2* pP, float* haveBeta){
  (void)haveBeta;
  if (beta){
    k_fwdzT<<<dim3(128,4,1), 256>>>(pP, 0, pC0, 1, pR, pP);
    k_rscopy<<<1,32>>>();
  } else {
    k_fwdzT<<<dim3(128,4,1), 256>>>(vin, 0, pC0, 0, 0, 0);
  }
  k_plane1 <<<128, 512, PLANE_SMEM>>>(pC0, pSe, pTmp);
  k_zfuseT <<<dim3(128,4,NR), 256>>>(pTmp, pM8);
  k_plane2 <<<128, 512, PLANE_SMEM>>>(pTmp, pSe, pC0);
  k_invzT_ap<<<dim3(128,4), 256>>>(pC0, vout, (beta||vin) ? (beta?pP:vin) : 0, LAMBDA, pPart);
}

extern "C" void kernel_launch(void* const* d_in, const int* in_sizes, int n_in,
                              void* d_out, int out_size){
  const float* x      = (const float*)d_in[0];
  const float* x1     = (const float*)d_in[1];
  const float* x3     = (const float*)d_in[2];
  const float* init_x = (const float*)d_in[3];
  const float* smv    = (const float*)d_in[4];
  float* out = (float*)d_out;

  float2 *pC0, *pTmp, *pB, *pXk, *pR, *pP, *pAp;
  float *pSe, *pRs, *pPAp, *pRsn, *pPart;
  uchar2 *pM8;
  cudaGetSymbolAddress((void**)&pC0,  d_C0);
  cudaGetSymbolAddress((void**)&pTmp, d_tmp);
  cudaGetSymbolAddress((void**)&pSe,  d_Se);
  cudaGetSymbolAddress((void**)&pM8,  d_m8);
  cudaGetSymbolAddress((void**)&pB,   d_bb);
  cudaGetSymbolAddress((void**)&pXk,  d_xk);
  cudaGetSymbolAddress((void**)&pR,   d_rr);
  cudaGetSymbolAddress((void**)&pP,   d_pp);
  cudaGetSymbolAddress((void**)&pAp,  d_Ap);
  cudaGetSymbolAddress((void**)&pRs,  d_rs);
  cudaGetSymbolAddress((void**)&pPAp, d_pAp);
  cudaGetSymbolAddress((void**)&pRsn, d_rsn);
  cudaGetSymbolAddress((void**)&pPart,d_part);

  cudaFuncSetAttribute(k_plane1, cudaFuncAttributeMaxDynamicSharedMemorySize, PLANE_SMEM);
  cudaFuncSetAttribute(k_plane2, cudaFuncAttributeMaxDynamicSharedMemorySize, PLANE_SMEM);

  k_initW <<<1,128>>>();
  k_prep  <<<VOL/256, 256>>>(x, x1, x3, init_x);
  k_prepSe<<<dim3(VOL/256, NR), 256>>>(smv);

  // b = smv_adj( m * (w3*x) ); wx packed is in d_rr
  k_fwdzT  <<<dim3(128,4,NR), 256>>>(pR, pM8, pTmp, 0, 0, 0);
  k_plane2 <<<128, 512, PLANE_SMEM>>>(pTmp, pSe, pC0);
  k_invzT_ap<<<dim3(128,4), 256>>>(pC0, pB, 0, 0.f, 0);

  // r0 = b - A(x0); p = r0; rs = <r0,r0>
  applyA(pXk, pAp, 0, 0, pC0, pTmp, pSe, pM8, pR, pP, 0);
  k_init_r<<<256, 256>>>(pPart);
  k_fin<<<NB, 256>>>(pPart, pRs, 256);

  for (int it=0; it<NITER; ++it){
    applyA(pP, pAp, pPart, (it>0)?1:0, pC0, pTmp, pSe, pM8, pR, pP, 0);
    k_fin<<<NB, 256>>>(pPart, pPAp, 512);
    k_update1<<<256, 256>>>(pPart);
    k_fin<<<NB, 256>>>(pPart, pRsn, 256);
  }

  k_unpack<<<VOL/256, 256>>>(out);
}

// round 6
// speedup vs baseline: 1.3648x; 1.1769x over previous
#include <cuda_runtime.h>
#include <cstdint>

#define NXX 128
#define VOL (128*128*128)
#define NB  2
#define NR  3
#define LAMBDA 1e-3f
#define EPSI   1e-12f
#define NITER  10
#define INV128f 0.0078125f
#define PLANE_SMEM 132096   // 2*16512 floats * 4 bytes

// ---------------------------------------------------------------------------
// Buffers. CG vectors packed float2 (x=batch0, y=batch1), natural [x][y][z].
// C0/tmp transposed [zp][x][y] (y contig). Se permuted [zp][yp][xp].
// ---------------------------------------------------------------------------
static __device__ float2 d_C0 [VOL];
static __device__ float2 d_tmp[NR*VOL];
static __device__ float  d_Se [NR*VOL];
static __device__ uchar2 d_m8 [NR*VOL];
static __device__ float2 d_bb [VOL];
static __device__ float2 d_xk [VOL];
static __device__ float2 d_rr [VOL];
static __device__ float2 d_pp [VOL];
static __device__ float2 d_Ap [VOL];
static __device__ float2 d_W  [NXX];
static __device__ float  d_rs [NB];
static __device__ float  d_pAp[NB];
static __device__ float  d_rsn[NB];
static __device__ float  d_part[NB*1024];

__device__ __forceinline__ float2 c_add(float2 a, float2 b){ return make_float2(a.x+b.x, a.y+b.y); }
__device__ __forceinline__ float2 c_sub(float2 a, float2 b){ return make_float2(a.x-b.x, a.y-b.y); }
__device__ __forceinline__ float2 c_mul(float2 a, float2 b){ return make_float2(a.x*b.x-a.y*b.y, a.x*b.y+a.y*b.x); }
__device__ __forceinline__ float2 c_mulc(float2 a, float2 w){ return make_float2(a.x*w.x+a.y*w.y, a.y*w.x-a.x*w.y); }

// per-lane register twiddles (kernel-invariant)
struct Tw { float2 s16,s8,s4,s2,f1,f2,f3; };
__device__ __forceinline__ Tw load_tw(int l){
  Tw t;
  t.s16=d_W[(l&15)<<2]; t.s8=d_W[(l&7)<<3]; t.s4=d_W[(l&3)<<4]; t.s2=d_W[(l&1)<<5];
  t.f1=d_W[l]; t.f2=d_W[2*l]; t.f3=d_W[3*l];
  return t;
}

__device__ __forceinline__ void fstage(float2 v[4], int l, int d, float2 w){
  bool up = (l & d) != 0;
  #pragma unroll
  for (int k=0;k<4;k++){
    float2 p;
    p.x=__shfl_xor_sync(0xffffffffu, v[k].x, d);
    p.y=__shfl_xor_sync(0xffffffffu, v[k].y, d);
    v[k] = up ? c_mul(c_sub(p, v[k]), w) : c_add(v[k], p);
  }
}
__device__ __forceinline__ void fstage1(float2 v[4], int l){
  bool up = (l & 1) != 0;
  #pragma unroll
  for (int k=0;k<4;k++){
    float2 p;
    p.x=__shfl_xor_sync(0xffffffffu, v[k].x, 1);
    p.y=__shfl_xor_sync(0xffffffffu, v[k].y, 1);
    v[k] = up ? c_sub(p, v[k]) : c_add(v[k], p);
  }
}
__device__ __forceinline__ void istage(float2 v[4], int l, int d, float2 w){
  bool up = (l & d) != 0;
  #pragma unroll
  for (int k=0;k<4;k++){
    float2 own = up ? c_mulc(v[k], w) : v[k];
    float2 p;
    p.x=__shfl_xor_sync(0xffffffffu, own.x, d);
    p.y=__shfl_xor_sync(0xffffffffu, own.y, d);
    v[k] = up ? c_sub(p, own) : c_add(own, p);
  }
}
__device__ __forceinline__ void istage1(float2 v[4], int l){
  bool up = (l & 1) != 0;
  #pragma unroll
  for (int k=0;k<4;k++){
    float2 p;
    p.x=__shfl_xor_sync(0xffffffffu, v[k].x, 1);
    p.y=__shfl_xor_sync(0xffffffffu, v[k].y, 1);
    v[k] = up ? c_sub(p, v[k]) : c_add(v[k], p);
  }
}

// Warp 128-pt FFT. Lane l, reg k holds x[l+32k] (natural) on forward input.
// Forward output: position p=l+32k holds X[k(p)], k(p)=(p>>5)+4*bitrev5(p&31).
// Inverse consumes that layout, returns natural order scaled 1/128.
__device__ __forceinline__ void wf_fwd(float2 v[4], const Tw& t, int l){
  float2 t0=c_add(v[0],v[2]), t1=c_sub(v[0],v[2]);
  float2 t2=c_add(v[1],v[3]), t3=c_sub(v[1],v[3]);
  float2 mi3 = make_float2(t3.y,-t3.x);
  v[0]=c_add(t0,t2); v[2]=c_sub(t0,t2);
  v[1]=c_add(t1,mi3); v[3]=c_sub(t1,mi3);
  v[1]=c_mul(v[1], t.f1);
  v[2]=c_mul(v[2], t.f2);
  v[3]=c_mul(v[3], t.f3);
  fstage(v,l,16,t.s16);
  fstage(v,l,8, t.s8);
  fstage(v,l,4, t.s4);
  fstage(v,l,2, t.s2);
  fstage1(v,l);
}
__device__ __forceinline__ void wf_inv(float2 v[4], const Tw& t, int l){
  istage1(v,l);
  istage(v,l,2, t.s2);
  istage(v,l,4, t.s4);
  istage(v,l,8, t.s8);
  istage(v,l,16,t.s16);
  float2 a1=c_mulc(v[1],t.f1), a2=c_mulc(v[2],t.f2), a3=c_mulc(v[3],t.f3);
  v[0]=make_float2(v[0].x*INV128f, v[0].y*INV128f);
  v[1]=make_float2(a1.x*INV128f, a1.y*INV128f);
  v[2]=make_float2(a2.x*INV128f, a2.y*INV128f);
  v[3]=make_float2(a3.x*INV128f, a3.y*INV128f);
  float2 t0=c_add(v[0],v[2]), t1=c_sub(v[0],v[2]);
  float2 t2=c_add(v[1],v[3]), t3=c_sub(v[1],v[3]);
  float2 pi3 = make_float2(-t3.y, t3.x);
  v[0]=c_add(t0,t2); v[2]=c_sub(t0,t2);
  v[1]=c_add(t1,pi3); v[3]=c_sub(t1,pi3);
}

// ---------------------------------------------------------------------------
// init kernels
// ---------------------------------------------------------------------------
__global__ void k_initW(){
  int k = threadIdx.x;
  if (k < NXX){
    float s, c;
    sincospif(-(float)k/64.0f, &s, &c);
    d_W[k] = make_float2(c, s);
  }
}

__global__ __launch_bounds__(256) void k_prep(const float* __restrict__ x,
                                              const float* __restrict__ x1,
                                              const float* __restrict__ x3,
                                              const float* __restrict__ ix){
  int i = blockIdx.x*256 + threadIdx.x;
  d_xk[i] = make_float2(ix[i], ix[VOL+i]);
  d_rr[i] = make_float2(x[i]*x3[i], x[VOL+i]*x3[VOL+i]);
  #pragma unroll
  for (int r=0;r<NR;r++){
    float m0 = x1[(size_t)i*NR + r];
    float m1 = x1[(size_t)VOL*NR + (size_t)i*NR + r];
    d_m8[(size_t)r*VOL + i] = make_uchar2(m0 != 0.f, m1 != 0.f);
  }
}

__device__ __forceinline__ int kofp(int p){
  int l = p & 31, k2 = p >> 5;
  return k2 + 4*(int)(__brev((unsigned)l) >> 27);
}

__global__ __launch_bounds__(256) void k_prepSe(const float* __restrict__ smv){
  int r = blockIdx.y;
  int o = blockIdx.x*256 + threadIdx.x;
  int zp = o>>14, yp = (o>>7)&127, xp = o&127;
  int kx = kofp(xp), ky = kofp(yp), kz = kofp(zp);
  int i1 = (kx<<14) | (ky<<7) | kz;
  int i2 = (((128-kx)&127)<<14) | (((128-ky)&127)<<7) | ((128-kz)&127);
  d_Se[(size_t)r*VOL + o] = 0.5f*(smv[(size_t)r*VOL + i1] + smv[(size_t)r*VOL + i2]);
}

// ---------------------------------------------------------------------------
// fwd-z with transpose-out: in natural [x][y][z] -> out[f][zp][x][y].
// Optional spatial mask per radius f; optional fused p = r + beta*p update.
// ---------------------------------------------------------------------------
__global__ __launch_bounds__(256) void k_fwdzT(const float2* __restrict__ in,
                                               const uchar2* __restrict__ mask,
                                               float2* __restrict__ out,
                                               int betaFlag,
                                               const float2* __restrict__ rvec,
                                               float2* __restrict__ pwrite){
  __shared__ float tR[128*33], tI[128*33];
  int tid=threadIdx.x, l=tid&31, w=tid>>5;
  int x=blockIdx.x, yt=blockIdx.y, f=blockIdx.z;
  Tw tw = load_tw(l);
  float b0=0.f, b1=0.f;
  if (betaFlag){ b0 = d_rsn[0]/(d_rs[0]+EPSI); b1 = d_rsn[1]/(d_rs[1]+EPSI); }
  const uchar2* pm = mask ? (mask + (size_t)f*VOL) : (const uchar2*)0;
  for (int ln=0; ln<4; ln++){
    int c=(w<<2)+ln;
    int y=(yt<<5)+c;
    size_t base=(size_t)x*16384 + (size_t)y*128;
    float2 v[4];
    #pragma unroll
    for (int k=0;k<4;k++){
      int z=l+(k<<5);
      float2 t=in[base+z];
      if (betaFlag){
        float2 rv=rvec[base+z];
        t=make_float2(rv.x+b0*t.x, rv.y+b1*t.y);
        pwrite[base+z]=t;
      }
      if (pm){ uchar2 m=pm[base+z]; t.x*=(float)m.x; t.y*=(float)m.y; }
      v[k]=t;
    }
    wf_fwd(v,tw,l);
    #pragma unroll
    for (int k=0;k<4;k++){ int p=l+(k<<5); tR[p*33+c]=v[k].x; tI[p*33+c]=v[k].y; }
  }
  __syncthreads();
  float2* po = out + (size_t)f*VOL + (size_t)x*128 + ((size_t)yt<<5);
  for (int i=tid;i<4096;i+=256){
    int zp=i>>5, c=i&31;
    po[(size_t)zp*16384 + c] = make_float2(tR[zp*33+c], tI[zp*33+c]);
  }
}

// ---------------------------------------------------------------------------
// plane spread: per zp: fwd-y (global->regs), fwd-x (F in regs), per r:
// *Se_r, inv-x, inv-y (regs->global into tmp[r][zp][x][y]).
// ---------------------------------------------------------------------------
__global__ __launch_bounds__(512,1) void k_plane1(const float2* __restrict__ cin,
                                                  const float* __restrict__ Se,
                                                  float2* __restrict__ outT){
  extern __shared__ float ps[];
  float* pR=ps; float* pI=ps+16512;
  int tid=threadIdx.x, l=tid&31, w=tid>>5;   // 16 warps
  int zp=blockIdx.x;
  Tw tw = load_tw(l);
  const float2* pin = cin + (size_t)zp*16384;
  // fwd-y: rows (fixed x), read global directly
  for (int ln=0; ln<8; ln++){
    int x=(w<<3)+ln;
    float2 v[4];
    #pragma unroll
    for (int k=0;k<4;k++) v[k]=pin[x*128 + l+(k<<5)];
    wf_fwd(v,tw,l);
    #pragma unroll
    for (int k=0;k<4;k++){ int p=l+(k<<5); pR[x*129+p]=v[k].x; pI[x*129+p]=v[k].y; }
  }
  __syncthreads();
  // fwd-x: cols (fixed yp), keep F in regs
  float2 F[8][4];
  for (int ln=0; ln<8; ln++){
    int yc=(w<<3)+ln;
    #pragma unroll
    for (int k=0;k<4;k++){ int xi=l+(k<<5); F[ln][k]=make_float2(pR[xi*129+yc],pI[xi*129+yc]); }
    wf_fwd(F[ln],tw,l);
  }
  for (int r=0;r<NR;r++){
    __syncthreads();
    const float* pS = Se + (size_t)r*VOL + (size_t)zp*16384;
    for (int ln=0; ln<8; ln++){
      int yc=(w<<3)+ln;
      float2 v[4];
      #pragma unroll
      for (int k=0;k<4;k++){
        float s=pS[yc*128 + l+(k<<5)];
        v[k]=make_float2(F[ln][k].x*s, F[ln][k].y*s);
      }
      wf_inv(v,tw,l);
      #pragma unroll
      for (int k=0;k<4;k++){ int xi=l+(k<<5); pR[xi*129+yc]=v[k].x; pI[xi*129+yc]=v[k].y; }
    }
    __syncthreads();
    float2* po = outT + (size_t)r*VOL + (size_t)zp*16384;
    for (int ln=0; ln<8; ln++){
      int x=(w<<3)+ln;
      float2 v[4];
      #pragma unroll
      for (int k=0;k<4;k++){ int y=l+(k<<5); v[k]=make_float2(pR[x*129+y],pI[x*129+y]); }
      wf_inv(v,tw,l);
      #pragma unroll
      for (int k=0;k<4;k++) po[x*128 + l+(k<<5)] = v[k];
    }
  }
}

// ---------------------------------------------------------------------------
// fused z on tmp[r]: inv-z, spatial mask, fwd-z (in-place, transposed layout).
// ---------------------------------------------------------------------------
__global__ __launch_bounds__(256) void k_zfuseT(float2* __restrict__ io,
                                                const uchar2* __restrict__ mask){
  __shared__ float tR[128*33], tI[128*33];
  int tid=threadIdx.x, l=tid&31, w=tid>>5;
  int x=blockIdx.x, yt=blockIdx.y, f=blockIdx.z;
  Tw tw = load_tw(l);
  float2* p0 = io + (size_t)f*VOL + (size_t)x*128 + ((size_t)yt<<5);
  for (int i=tid;i<4096;i+=256){
    int zp=i>>5, c=i&31;
    float2 t = p0[(size_t)zp*16384 + c];
    tR[zp*33+c]=t.x; tI[zp*33+c]=t.y;
  }
  __syncthreads();
  const uchar2* pm = mask + (size_t)f*VOL;
  for (int ln=0; ln<4; ln++){
    int c=(w<<2)+ln;
    int y=(yt<<5)+c;
    float2 v[4];
    #pragma unroll
    for (int k=0;k<4;k++){ int p=l+(k<<5); v[k]=make_float2(tR[p*33+c], tI[p*33+c]); }
    wf_inv(v,tw,l);
    size_t base=(size_t)x*16384 + (size_t)y*128;
    #pragma unroll
    for (int k=0;k<4;k++){
      int z=l+(k<<5);
      uchar2 m=pm[base+z];
      v[k].x*=(float)m.x; v[k].y*=(float)m.y;
    }
    wf_fwd(v,tw,l);
    #pragma unroll
    for (int k=0;k<4;k++){ int p=l+(k<<5); tR[p*33+c]=v[k].x; tI[p*33+c]=v[k].y; }
  }
  __syncthreads();
  for (int i=tid;i<4096;i+=256){
    int zp=i>>5, c=i&31;
    p0[(size_t)zp*16384 + c] = make_float2(tR[zp*33+c], tI[zp*33+c]);
  }
}

// ---------------------------------------------------------------------------
// plane gather: per zp: for r: fwd-y (global->regs->smem), fwd-x, acc += Se*(.),
// then inv-x, inv-y (regs->global C0[zp][x][y]).
// ---------------------------------------------------------------------------
__global__ __launch_bounds__(512,1) void k_plane2(const float2* __restrict__ tmp,
                                                  const float* __restrict__ Se,
                                                  float2* __restrict__ cout){
  extern __shared__ float ps[];
  float* pR=ps; float* pI=ps+16512;
  int tid=threadIdx.x, l=tid&31, w=tid>>5;
  int zp=blockIdx.x;
  Tw tw = load_tw(l);
  float2 acc[8][4];
  #pragma unroll
  for (int a=0;a<8;a++)
    #pragma unroll
    for (int k=0;k<4;k++) acc[a][k]=make_float2(0.f,0.f);
  for (int r=0;r<NR;r++){
    const float2* pin = tmp + (size_t)r*VOL + (size_t)zp*16384;
    __syncthreads();
    for (int ln=0; ln<8; ln++){             // fwd-y from global
      int x=(w<<3)+ln;
      float2 v[4];
      #pragma unroll
      for (int k=0;k<4;k++) v[k]=pin[x*128 + l+(k<<5)];
      wf_fwd(v,tw,l);
      #pragma unroll
      for (int k=0;k<4;k++){ int p=l+(k<<5); pR[x*129+p]=v[k].x; pI[x*129+p]=v[k].y; }
    }
    __syncthreads();
    const float* pS = Se + (size_t)r*VOL + (size_t)zp*16384;
    for (int ln=0; ln<8; ln++){             // fwd-x + accumulate
      int yc=(w<<3)+ln;
      float2 v[4];
      #pragma unroll
      for (int k=0;k<4;k++){ int xi=l+(k<<5); v[k]=make_float2(pR[xi*129+yc],pI[xi*129+yc]); }
      wf_fwd(v,tw,l);
      #pragma unroll
      for (int k=0;k<4;k++){
        float s=pS[yc*128 + l+(k<<5)];
        acc[ln][k].x += v[k].x*s; acc[ln][k].y += v[k].y*s;
      }
    }
  }
  for (int ln=0; ln<8; ln++){               // inv-x from acc (same addrs per lane)
    int yc=(w<<3)+ln;
    float2 v[4];
    #pragma unroll
    for (int k=0;k<4;k++) v[k]=acc[ln][k];
    wf_inv(v,tw,l);
    #pragma unroll
    for (int k=0;k<4;k++){ int xi=l+(k<<5); pR[xi*129+yc]=v[k].x; pI[xi*129+yc]=v[k].y; }
  }
  __syncthreads();
  float2* po = cout + (size_t)zp*16384;
  for (int ln=0; ln<8; ln++){               // inv-y -> global direct
    int x=(w<<3)+ln;
    float2 v[4];
    #pragma unroll
    for (int k=0;k<4;k++){ int y=l+(k<<5); v[k]=make_float2(pR[x*129+y],pI[x*129+y]); }
    wf_inv(v,tw,l);
    #pragma unroll
    for (int k=0;k<4;k++) po[x*128 + l+(k<<5)] = v[k];
  }
}

// ---------------------------------------------------------------------------
// inv-z from transposed -> natural Ap = (.) + lam*p, fused partial dot(p,Ap)
// ---------------------------------------------------------------------------
__global__ __launch_bounds__(256) void k_invzT_ap(const float2* __restrict__ cin,
                                                  float2* __restrict__ outAp,
                                                  const float2* __restrict__ pvec,
                                                  float lam, float* __restrict__ part){
  __shared__ float tR[128*33], tI[128*33];
  __shared__ float sm0[256], sm1[256];
  int tid=threadIdx.x, l=tid&31, w=tid>>5;
  int x=blockIdx.x, yt=blockIdx.y;
  Tw tw = load_tw(l);
  const float2* p0 = cin + (size_t)x*128 + ((size_t)yt<<5);
  for (int i=tid;i<4096;i+=256){
    int zp=i>>5, c=i&31;
    float2 t = p0[(size_t)zp*16384 + c];
    tR[zp*33+c]=t.x; tI[zp*33+c]=t.y;
  }
  __syncthreads();
  float s0=0.f, s1=0.f;
  for (int ln=0; ln<4; ln++){
    int c=(w<<2)+ln, y=(yt<<5)+c;
    float2 v[4];
    #pragma unroll
    for (int k=0;k<4;k++){ int p=l+(k<<5); v[k]=make_float2(tR[p*33+c], tI[p*33+c]); }
    wf_inv(v,tw,l);
    size_t base=(size_t)x*16384 + (size_t)y*128;
    #pragma unroll
    for (int k=0;k<4;k++){
      int z=l+(k<<5);
      float2 ap=v[k];
      if (pvec){
        float2 pv=pvec[base+z];
        ap.x+=lam*pv.x; ap.y+=lam*pv.y;
        s0+=pv.x*ap.x; s1+=pv.y*ap.y;
      }
      outAp[base+z]=ap;
    }
  }
  if (part){
    sm0[tid]=s0; sm1[tid]=s1; __syncthreads();
    for (int s=128;s>0;s>>=1){ if(tid<s){sm0[tid]+=sm0[tid+s];sm1[tid]+=sm1[tid+s];} __syncthreads(); }
    if (tid==0){ int b=blockIdx.x*4+blockIdx.y; part[b]=sm0[0]; part[1024+b]=sm1[0]; }
  }
}

// ---------------------------------------------------------------------------
// CG scalar machinery
// ---------------------------------------------------------------------------
__global__ void k_fin(const float* __restrict__ part, float* __restrict__ out, int n){
  __shared__ float sm[256];
  int b = blockIdx.x, t = threadIdx.x;
  float s = 0.f;
  for (int jj=t; jj<n; jj+=256) s += part[b*1024 + jj];
  sm[t]=s; __syncthreads();
  for (int st=128; st>0; st>>=1){ if (t<st) sm[t]+=sm[t+st]; __syncthreads(); }
  if (t==0) out[b] = sm[0];
}

__global__ __launch_bounds__(256) void k_init_r(float* __restrict__ part){
  __shared__ float sm0[256], sm1[256];
  int t = threadIdx.x;
  float s0=0.f, s1=0.f;
  for (int i=blockIdx.x*256+t; i<VOL; i+=256*256){
    float2 v = make_float2(d_bb[i].x - d_Ap[i].x, d_bb[i].y - d_Ap[i].y);
    d_rr[i]=v; d_pp[i]=v;
    s0 += v.x*v.x; s1 += v.y*v.y;
  }
  sm0[t]=s0; sm1[t]=s1; __syncthreads();
  for (int st=128; st>0; st>>=1){ if (t<st){ sm0[t]+=sm0[t+st]; sm1[t]+=sm1[t+st]; } __syncthreads(); }
  if (t==0){ part[blockIdx.x]=sm0[0]; part[1024+blockIdx.x]=sm1[0]; }
}

__global__ __launch_bounds__(256) void k_update1(float* __restrict__ part){
  __shared__ float sm0[256], sm1[256];
  int t = threadIdx.x;
  float a0 = d_rs[0] / (d_pAp[0] + EPSI);
  float a1 = d_rs[1] / (d_pAp[1] + EPSI);
  float s0=0.f, s1=0.f;
  for (int i=blockIdx.x*256+t; i<VOL; i+=256*256){
    float2 p = d_pp[i], ap = d_Ap[i], xk = d_xk[i], r = d_rr[i];
    xk.x += a0*p.x;  xk.y += a1*p.y;  d_xk[i]=xk;
    r.x  -= a0*ap.x; r.y  -= a1*ap.y; d_rr[i]=r;
    s0 += r.x*r.x;   s1 += r.y*r.y;
  }
  sm0[t]=s0; sm1[t]=s1; __syncthreads();
  for (int st=128; st>0; st>>=1){ if (t<st){ sm0[t]+=sm0[t+st]; sm1[t]+=sm1[t+st]; } __syncthreads(); }
  if (t==0){ part[blockIdx.x]=sm0[0]; part[1024+blockIdx.x]=sm1[0]; }
}

__global__ void k_rscopy(){
  if (threadIdx.x < NB) d_rs[threadIdx.x] = d_rsn[threadIdx.x];
}

__global__ __launch_bounds__(256) void k_unpack(float* __restrict__ out){
  int i = blockIdx.x*256 + threadIdx.x;
  float2 v = d_xk[i];
  out[i] = v.x;
  out[VOL+i] = v.y;
}

// ---------------------------------------------------------------------------
// Host side
// ---------------------------------------------------------------------------
static void applyA(const float2* vin, float2* vout, float* pPart, int beta,
                   float2* pC0, float2* pTmp, const float* pSe, const uchar2* pM8,
                   float2* pR, float2* pP){
  if (beta){
    k_fwdzT<<<dim3(128,4,1), 256>>>(pP, 0, pC0, 1, pR, pP);
    k_rscopy<<<1,32>>>();
  } else {
    k_fwdzT<<<dim3(128,4,1), 256>>>(vin, 0, pC0, 0, 0, 0);
  }
  k_plane1 <<<128, 512, PLANE_SMEM>>>(pC0, pSe, pTmp);
  k_zfuseT <<<dim3(128,4,NR), 256>>>(pTmp, pM8);
  k_plane2 <<<128, 512, PLANE_SMEM>>>(pTmp, pSe, pC0);
  k_invzT_ap<<<dim3(128,4), 256>>>(pC0, vout, beta ? pP : vin, LAMBDA, pPart);
}

extern "C" void kernel_launch(void* const* d_in, const int* in_sizes, int n_in,
                              void* d_out, int out_size){
  const float* x      = (const float*)d_in[0];
  const float* x1     = (const float*)d_in[1];
  const float* x3     = (const float*)d_in[2];
  const float* init_x = (const float*)d_in[3];
  const float* smv    = (const float*)d_in[4];
  float* out = (float*)d_out;

  float2 *pC0, *pTmp, *pB, *pXk, *pR, *pP, *pAp;
  float *pSe, *pRs, *pPAp, *pRsn, *pPart;
  uchar2 *pM8;
  cudaGetSymbolAddress((void**)&pC0,  d_C0);
  cudaGetSymbolAddress((void**)&pTmp, d_tmp);
  cudaGetSymbolAddress((void**)&pSe,  d_Se);
  cudaGetSymbolAddress((void**)&pM8,  d_m8);
  cudaGetSymbolAddress((void**)&pB,   d_bb);
  cudaGetSymbolAddress((void**)&pXk,  d_xk);
  cudaGetSymbolAddress((void**)&pR,   d_rr);
  cudaGetSymbolAddress((void**)&pP,   d_pp);
  cudaGetSymbolAddress((void**)&pAp,  d_Ap);
  cudaGetSymbolAddress((void**)&pRs,  d_rs);
  cudaGetSymbolAddress((void**)&pPAp, d_pAp);
  cudaGetSymbolAddress((void**)&pRsn, d_rsn);
  cudaGetSymbolAddress((void**)&pPart,d_part);

  cudaFuncSetAttribute(k_plane1, cudaFuncAttributeMaxDynamicSharedMemorySize, PLANE_SMEM);
  cudaFuncSetAttribute(k_plane2, cudaFuncAttributeMaxDynamicSharedMemorySize, PLANE_SMEM);

  k_initW <<<1,128>>>();
  k_prep  <<<VOL/256, 256>>>(x, x1, x3, init_x);
  k_prepSe<<<dim3(VOL/256, NR), 256>>>(smv);

  // b = smv_adj( m * (w3*x) ); wx packed is in d_rr
  k_fwdzT  <<<dim3(128,4,NR), 256>>>(pR, pM8, pTmp, 0, 0, 0);
  k_plane2 <<<128, 512, PLANE_SMEM>>>(pTmp, pSe, pC0);
  k_invzT_ap<<<dim3(128,4), 256>>>(pC0, pB, 0, 0.f, 0);

  // r0 = b - A(x0); p = r0; rs = <r0,r0>
  applyA(pXk, pAp, 0, 0, pC0, pTmp, pSe, pM8, pR, pP);
  k_init_r<<<256, 256>>>(pPart);
  k_fin<<<NB, 256>>>(pPart, pRs, 256);

  for (int it=0; it<NITER; ++it){
    applyA(pP, pAp, pPart, (it>0)?1:0, pC0, pTmp, pSe, pM8, pR, pP);
    k_fin<<<NB, 256>>>(pPart, pPAp, 512);
    k_update1<<<256, 256>>>(pPart);
    k_fin<<<NB, 256>>>(pPart, pRsn, 256);
  }

  k_unpack<<<VOL/256, 256>>>(out);
}

// round 7
// speedup vs baseline: 1.3778x; 1.0095x over previous
#include <cuda_runtime.h>
#include <cstdint>

#define NXX 128
#define VOL (128*128*128)
#define NB  2
#define NR  3
#define LAMBDA 1e-3f
#define EPSI   1e-12f
#define NITER  10
#define INV128f 0.0078125f
#define PLANE_SMEM 131072   // 16384 float2

// ---------------------------------------------------------------------------
// Buffers. CG vectors packed float2 (x=batch0, y=batch1), natural [x][y][z].
// C0/tmp transposed [zp][x][y] (y contig). Se permuted [zp][yp][xp].
// ---------------------------------------------------------------------------
static __device__ float2 d_C0 [VOL];
static __device__ float2 d_tmp[NR*VOL];
static __device__ float  d_Se [NR*VOL];
static __device__ uchar2 d_m8 [NR*VOL];
static __device__ float2 d_bb [VOL];
static __device__ float2 d_xk [VOL];
static __device__ float2 d_rr [VOL];
static __device__ float2 d_pp [VOL];
static __device__ float2 d_Ap [VOL];
static __device__ float2 d_W  [NXX];
static __device__ float  d_rs [NB];
static __device__ float  d_pAp[NB];
static __device__ float  d_rsn[NB];
static __device__ float  d_part[NB*1024];

__device__ __forceinline__ float2 c_add(float2 a, float2 b){ return make_float2(a.x+b.x, a.y+b.y); }
__device__ __forceinline__ float2 c_sub(float2 a, float2 b){ return make_float2(a.x-b.x, a.y-b.y); }
__device__ __forceinline__ float2 c_mul(float2 a, float2 b){ return make_float2(a.x*b.x-a.y*b.y, a.x*b.y+a.y*b.x); }
__device__ __forceinline__ float2 c_mulc(float2 a, float2 w){ return make_float2(a.x*w.x+a.y*w.y, a.y*w.x-a.x*w.y); }

// XOR-swizzled smem indexing (conflict-free in both transpose directions)
__device__ __forceinline__ int swz32 (int row, int col){ return (row<<5) + (col ^ (row&31)); }   // [128][32]
__device__ __forceinline__ int swz128(int row, int col){ return (row<<7) + (col ^ (row&31)); }   // [128][128]

// per-lane register twiddles (kernel-invariant)
struct Tw { float2 s16,s8,s4,s2,f1,f2,f3; };
__device__ __forceinline__ Tw load_tw(int l){
  Tw t;
  t.s16=d_W[(l&15)<<2]; t.s8=d_W[(l&7)<<3]; t.s4=d_W[(l&3)<<4]; t.s2=d_W[(l&1)<<5];
  t.f1=d_W[l]; t.f2=d_W[2*l]; t.f3=d_W[3*l];
  return t;
}

__device__ __forceinline__ void fstage(float2 v[4], int l, int d, float2 w){
  bool up = (l & d) != 0;
  #pragma unroll
  for (int k=0;k<4;k++){
    float2 p;
    p.x=__shfl_xor_sync(0xffffffffu, v[k].x, d);
    p.y=__shfl_xor_sync(0xffffffffu, v[k].y, d);
    v[k] = up ? c_mul(c_sub(p, v[k]), w) : c_add(v[k], p);
  }
}
__device__ __forceinline__ void fstage1(float2 v[4], int l){
  bool up = (l & 1) != 0;
  #pragma unroll
  for (int k=0;k<4;k++){
    float2 p;
    p.x=__shfl_xor_sync(0xffffffffu, v[k].x, 1);
    p.y=__shfl_xor_sync(0xffffffffu, v[k].y, 1);
    v[k] = up ? c_sub(p, v[k]) : c_add(v[k], p);
  }
}
__device__ __forceinline__ void istage(float2 v[4], int l, int d, float2 w){
  bool up = (l & d) != 0;
  #pragma unroll
  for (int k=0;k<4;k++){
    float2 own = up ? c_mulc(v[k], w) : v[k];
    float2 p;
    p.x=__shfl_xor_sync(0xffffffffu, own.x, d);
    p.y=__shfl_xor_sync(0xffffffffu, own.y, d);
    v[k] = up ? c_sub(p, own) : c_add(own, p);
  }
}
__device__ __forceinline__ void istage1(float2 v[4], int l){
  bool up = (l & 1) != 0;
  #pragma unroll
  for (int k=0;k<4;k++){
    float2 p;
    p.x=__shfl_xor_sync(0xffffffffu, v[k].x, 1);
    p.y=__shfl_xor_sync(0xffffffffu, v[k].y, 1);
    v[k] = up ? c_sub(p, v[k]) : c_add(v[k], p);
  }
}

// Warp 128-pt FFT. Lane l, reg k holds x[l+32k] (natural) on forward input.
// Forward output: position p=l+32k holds X[k(p)], k(p)=(p>>5)+4*bitrev5(p&31).
// Inverse consumes that layout, returns natural order scaled 1/128.
__device__ __forceinline__ void wf_fwd(float2 v[4], const Tw& t, int l){
  float2 t0=c_add(v[0],v[2]), t1=c_sub(v[0],v[2]);
  float2 t2=c_add(v[1],v[3]), t3=c_sub(v[1],v[3]);
  float2 mi3 = make_float2(t3.y,-t3.x);
  v[0]=c_add(t0,t2); v[2]=c_sub(t0,t2);
  v[1]=c_add(t1,mi3); v[3]=c_sub(t1,mi3);
  v[1]=c_mul(v[1], t.f1);
  v[2]=c_mul(v[2], t.f2);
  v[3]=c_mul(v[3], t.f3);
  fstage(v,l,16,t.s16);
  fstage(v,l,8, t.s8);
  fstage(v,l,4, t.s4);
  fstage(v,l,2, t.s2);
  fstage1(v,l);
}
__device__ __forceinline__ void wf_inv(float2 v[4], const Tw& t, int l){
  istage1(v,l);
  istage(v,l,2, t.s2);
  istage(v,l,4, t.s4);
  istage(v,l,8, t.s8);
  istage(v,l,16,t.s16);
  float2 a1=c_mulc(v[1],t.f1), a2=c_mulc(v[2],t.f2), a3=c_mulc(v[3],t.f3);
  v[0]=make_float2(v[0].x*INV128f, v[0].y*INV128f);
  v[1]=make_float2(a1.x*INV128f, a1.y*INV128f);
  v[2]=make_float2(a2.x*INV128f, a2.y*INV128f);
  v[3]=make_float2(a3.x*INV128f, a3.y*INV128f);
  float2 t0=c_add(v[0],v[2]), t1=c_sub(v[0],v[2]);
  float2 t2=c_add(v[1],v[3]), t3=c_sub(v[1],v[3]);
  float2 pi3 = make_float2(-t3.y, t3.x);
  v[0]=c_add(t0,t2); v[2]=c_sub(t0,t2);
  v[1]=c_add(t1,pi3); v[3]=c_sub(t1,pi3);
}

// ---------------------------------------------------------------------------
// init kernels
// ---------------------------------------------------------------------------
__global__ void k_initW(){
  int k = threadIdx.x;
  if (k < NXX){
    float s, c;
    sincospif(-(float)k/64.0f, &s, &c);
    d_W[k] = make_float2(c, s);
  }
}

__global__ __launch_bounds__(256) void k_prep(const float* __restrict__ x,
                                              const float* __restrict__ x1,
                                              const float* __restrict__ x3,
                                              const float* __restrict__ ix){
  int i = blockIdx.x*256 + threadIdx.x;
  d_xk[i] = make_float2(ix[i], ix[VOL+i]);
  d_rr[i] = make_float2(x[i]*x3[i], x[VOL+i]*x3[VOL+i]);
  #pragma unroll
  for (int r=0;r<NR;r++){
    float m0 = x1[(size_t)i*NR + r];
    float m1 = x1[(size_t)VOL*NR + (size_t)i*NR + r];
    d_m8[(size_t)r*VOL + i] = make_uchar2(m0 != 0.f, m1 != 0.f);
  }
}

__device__ __forceinline__ int kofp(int p){
  int l = p & 31, k2 = p >> 5;
  return k2 + 4*(int)(__brev((unsigned)l) >> 27);
}

__global__ __launch_bounds__(256) void k_prepSe(const float* __restrict__ smv){
  int r = blockIdx.y;
  int o = blockIdx.x*256 + threadIdx.x;
  int zp = o>>14, yp = (o>>7)&127, xp = o&127;
  int kx = kofp(xp), ky = kofp(yp), kz = kofp(zp);
  int i1 = (kx<<14) | (ky<<7) | kz;
  int i2 = (((128-kx)&127)<<14) | (((128-ky)&127)<<7) | ((128-kz)&127);
  d_Se[(size_t)r*VOL + o] = 0.5f*(smv[(size_t)r*VOL + i1] + smv[(size_t)r*VOL + i2]);
}

// ---------------------------------------------------------------------------
// fwd-z with transpose-out: in natural [x][y][z] -> out[f][zp][x][y].
// Optional spatial mask per radius f; optional fused p = r + beta*p update.
// ---------------------------------------------------------------------------
__global__ __launch_bounds__(256) void k_fwdzT(const float2* __restrict__ in,
                                               const uchar2* __restrict__ mask,
                                               float2* __restrict__ out,
                                               int betaFlag,
                                               const float2* __restrict__ rvec,
                                               float2* __restrict__ pwrite){
  __shared__ float2 sT[4096];
  int tid=threadIdx.x, l=tid&31, w=tid>>5;
  int x=blockIdx.x, yt=blockIdx.y, f=blockIdx.z;
  Tw tw = load_tw(l);
  float b0=0.f, b1=0.f;
  if (betaFlag){ b0 = d_rsn[0]/(d_rs[0]+EPSI); b1 = d_rsn[1]/(d_rs[1]+EPSI); }
  const uchar2* pm = mask ? (mask + (size_t)f*VOL) : (const uchar2*)0;
  for (int ln=0; ln<4; ln++){
    int c=(w<<2)+ln;
    int y=(yt<<5)+c;
    size_t base=(size_t)x*16384 + (size_t)y*128;
    float2 v[4];
    #pragma unroll
    for (int k=0;k<4;k++){
      int z=l+(k<<5);
      float2 t=in[base+z];
      if (betaFlag){
        float2 rv=rvec[base+z];
        t=make_float2(rv.x+b0*t.x, rv.y+b1*t.y);
        pwrite[base+z]=t;
      }
      if (pm){ uchar2 m=pm[base+z]; t.x*=(float)m.x; t.y*=(float)m.y; }
      v[k]=t;
    }
    wf_fwd(v,tw,l);
    #pragma unroll
    for (int k=0;k<4;k++) sT[swz32(l+(k<<5), c)] = v[k];
  }
  __syncthreads();
  float2* po = out + (size_t)f*VOL + (size_t)x*128 + ((size_t)yt<<5);
  for (int i=tid;i<2048;i+=256){
    int zp=i>>4, c2=(i&15)<<1;
    float2 a = sT[swz32(zp,c2)];
    float2 b = sT[swz32(zp,c2|1)];
    *reinterpret_cast<float4*>(po + (size_t)zp*16384 + c2) = make_float4(a.x,a.y,b.x,b.y);
  }
}

// ---------------------------------------------------------------------------
// plane spread: per zp: fwd-y (global->regs), fwd-x (F in regs), per r:
// *Se_r, inv-x, inv-y (regs->global into tmp[r][zp][x][y]).
// ---------------------------------------------------------------------------
__global__ __launch_bounds__(512,1) void k_plane1(const float2* __restrict__ cin,
                                                  const float* __restrict__ Se,
                                                  float2* __restrict__ outT){
  extern __shared__ unsigned char smraw[];
  float2* sP = reinterpret_cast<float2*>(smraw);
  int tid=threadIdx.x, l=tid&31, w=tid>>5;   // 16 warps
  int zp=blockIdx.x;
  Tw tw = load_tw(l);
  const float2* pin = cin + (size_t)zp*16384;
  for (int ln=0; ln<8; ln++){                 // fwd-y
    int x=(w<<3)+ln;
    float2 v[4];
    #pragma unroll
    for (int k=0;k<4;k++) v[k]=pin[x*128 + l+(k<<5)];
    wf_fwd(v,tw,l);
    #pragma unroll
    for (int k=0;k<4;k++) sP[swz128(x, l+(k<<5))] = v[k];
  }
  __syncthreads();
  float2 F[8][4];
  for (int ln=0; ln<8; ln++){                 // fwd-x, keep F in regs
    int yc=(w<<3)+ln;
    #pragma unroll
    for (int k=0;k<4;k++) F[ln][k] = sP[swz128(l+(k<<5), yc)];
    wf_fwd(F[ln],tw,l);
  }
  for (int r=0;r<NR;r++){
    __syncthreads();
    const float* pS = Se + (size_t)r*VOL + (size_t)zp*16384;
    for (int ln=0; ln<8; ln++){
      int yc=(w<<3)+ln;
      float2 v[4];
      #pragma unroll
      for (int k=0;k<4;k++){
        float s=pS[yc*128 + l+(k<<5)];
        v[k]=make_float2(F[ln][k].x*s, F[ln][k].y*s);
      }
      wf_inv(v,tw,l);
      #pragma unroll
      for (int k=0;k<4;k++) sP[swz128(l+(k<<5), yc)] = v[k];
    }
    __syncthreads();
    float2* po = outT + (size_t)r*VOL + (size_t)zp*16384;
    for (int ln=0; ln<8; ln++){
      int x=(w<<3)+ln;
      float2 v[4];
      #pragma unroll
      for (int k=0;k<4;k++) v[k] = sP[swz128(x, l+(k<<5))];
      wf_inv(v,tw,l);
      #pragma unroll
      for (int k=0;k<4;k++) po[x*128 + l+(k<<5)] = v[k];
    }
  }
}

// ---------------------------------------------------------------------------
// fused z on tmp[r]: inv-z, spatial mask, fwd-z (in-place, transposed layout).
// ---------------------------------------------------------------------------
__global__ __launch_bounds__(256) void k_zfuseT(float2* __restrict__ io,
                                                const uchar2* __restrict__ mask){
  __shared__ float2 sT[4096];
  int tid=threadIdx.x, l=tid&31, w=tid>>5;
  int x=blockIdx.x, yt=blockIdx.y, f=blockIdx.z;
  Tw tw = load_tw(l);
  float2* p0 = io + (size_t)f*VOL + (size_t)x*128 + ((size_t)yt<<5);
  for (int i=tid;i<2048;i+=256){
    int zp=i>>4, c2=(i&15)<<1;
    float4 v4 = *reinterpret_cast<const float4*>(p0 + (size_t)zp*16384 + c2);
    sT[swz32(zp,c2)]   = make_float2(v4.x, v4.y);
    sT[swz32(zp,c2|1)] = make_float2(v4.z, v4.w);
  }
  __syncthreads();
  const uchar2* pm = mask + (size_t)f*VOL;
  for (int ln=0; ln<4; ln++){
    int c=(w<<2)+ln;
    int y=(yt<<5)+c;
    float2 v[4];
    #pragma unroll
    for (int k=0;k<4;k++) v[k] = sT[swz32(l+(k<<5), c)];
    wf_inv(v,tw,l);
    size_t base=(size_t)x*16384 + (size_t)y*128;
    #pragma unroll
    for (int k=0;k<4;k++){
      int z=l+(k<<5);
      uchar2 m=pm[base+z];
      v[k].x*=(float)m.x; v[k].y*=(float)m.y;
    }
    wf_fwd(v,tw,l);
    #pragma unroll
    for (int k=0;k<4;k++) sT[swz32(l+(k<<5), c)] = v[k];
  }
  __syncthreads();
  for (int i=tid;i<2048;i+=256){
    int zp=i>>4, c2=(i&15)<<1;
    float2 a = sT[swz32(zp,c2)];
    float2 b = sT[swz32(zp,c2|1)];
    *reinterpret_cast<float4*>(p0 + (size_t)zp*16384 + c2) = make_float4(a.x,a.y,b.x,b.y);
  }
}

// ---------------------------------------------------------------------------
// plane gather: per zp: for r: fwd-y, fwd-x, acc += Se*(.), then inv-x,
// inv-y (regs->global C0[zp][x][y]).
// ---------------------------------------------------------------------------
__global__ __launch_bounds__(512,1) void k_plane2(const float2* __restrict__ tmp,
                                                  const float* __restrict__ Se,
                                                  float2* __restrict__ cout){
  extern __shared__ unsigned char smraw[];
  float2* sP = reinterpret_cast<float2*>(smraw);
  int tid=threadIdx.x, l=tid&31, w=tid>>5;
  int zp=blockIdx.x;
  Tw tw = load_tw(l);
  float2 acc[8][4];
  #pragma unroll
  for (int a=0;a<8;a++)
    #pragma unroll
    for (int k=0;k<4;k++) acc[a][k]=make_float2(0.f,0.f);
  for (int r=0;r<NR;r++){
    const float2* pin = tmp + (size_t)r*VOL + (size_t)zp*16384;
    __syncthreads();
    for (int ln=0; ln<8; ln++){             // fwd-y
      int x=(w<<3)+ln;
      float2 v[4];
      #pragma unroll
      for (int k=0;k<4;k++) v[k]=pin[x*128 + l+(k<<5)];
      wf_fwd(v,tw,l);
      #pragma unroll
      for (int k=0;k<4;k++) sP[swz128(x, l+(k<<5))] = v[k];
    }
    __syncthreads();
    const float* pS = Se + (size_t)r*VOL + (size_t)zp*16384;
    for (int ln=0; ln<8; ln++){             // fwd-x + accumulate
      int yc=(w<<3)+ln;
      float2 v[4];
      #pragma unroll
      for (int k=0;k<4;k++) v[k] = sP[swz128(l+(k<<5), yc)];
      wf_fwd(v,tw,l);
      #pragma unroll
      for (int k=0;k<4;k++){
        float s=pS[yc*128 + l+(k<<5)];
        acc[ln][k].x += v[k].x*s; acc[ln][k].y += v[k].y*s;
      }
    }
  }
  __syncthreads();
  for (int ln=0; ln<8; ln++){               // inv-x from acc
    int yc=(w<<3)+ln;
    float2 v[4];
    #pragma unroll
    for (int k=0;k<4;k++) v[k]=acc[ln][k];
    wf_inv(v,tw,l);
    #pragma unroll
    for (int k=0;k<4;k++) sP[swz128(l+(k<<5), yc)] = v[k];
  }
  __syncthreads();
  float2* po = cout + (size_t)zp*16384;
  for (int ln=0; ln<8; ln++){               // inv-y -> global direct
    int x=(w<<3)+ln;
    float2 v[4];
    #pragma unroll
    for (int k=0;k<4;k++) v[k] = sP[swz128(x, l+(k<<5))];
    wf_inv(v,tw,l);
    #pragma unroll
    for (int k=0;k<4;k++) po[x*128 + l+(k<<5)] = v[k];
  }
}

// ---------------------------------------------------------------------------
// inv-z from transposed -> natural Ap = (.) + lam*p, fused partial dot(p,Ap)
// ---------------------------------------------------------------------------
__global__ __launch_bounds__(256) void k_invzT_ap(const float2* __restrict__ cin,
                                                  float2* __restrict__ outAp,
                                                  const float2* __restrict__ pvec,
                                                  float lam, float* __restrict__ part){
  __shared__ float2 sT[4096];
  __shared__ float sm0[256], sm1[256];
  int tid=threadIdx.x, l=tid&31, w=tid>>5;
  int x=blockIdx.x, yt=blockIdx.y;
  Tw tw = load_tw(l);
  const float2* p0 = cin + (size_t)x*128 + ((size_t)yt<<5);
  for (int i=tid;i<2048;i+=256){
    int zp=i>>4, c2=(i&15)<<1;
    float4 v4 = *reinterpret_cast<const float4*>(p0 + (size_t)zp*16384 + c2);
    sT[swz32(zp,c2)]   = make_float2(v4.x, v4.y);
    sT[swz32(zp,c2|1)] = make_float2(v4.z, v4.w);
  }
  __syncthreads();
  float s0=0.f, s1=0.f;
  for (int ln=0; ln<4; ln++){
    int c=(w<<2)+ln, y=(yt<<5)+c;
    float2 v[4];
    #pragma unroll
    for (int k=0;k<4;k++) v[k] = sT[swz32(l+(k<<5), c)];
    wf_inv(v,tw,l);
    size_t base=(size_t)x*16384 + (size_t)y*128;
    #pragma unroll
    for (int k=0;k<4;k++){
      int z=l+(k<<5);
      float2 ap=v[k];
      if (pvec){
        float2 pv=pvec[base+z];
        ap.x+=lam*pv.x; ap.y+=lam*pv.y;
        s0+=pv.x*ap.x; s1+=pv.y*ap.y;
      }
      outAp[base+z]=ap;
    }
  }
  if (part){
    sm0[tid]=s0; sm1[tid]=s1; __syncthreads();
    for (int s=128;s>0;s>>=1){ if(tid<s){sm0[tid]+=sm0[tid+s];sm1[tid]+=sm1[tid+s];} __syncthreads(); }
    if (tid==0){ int b=blockIdx.x*4+blockIdx.y; part[b]=sm0[0]; part[1024+b]=sm1[0]; }
  }
}

// ---------------------------------------------------------------------------
// CG scalar machinery
// ---------------------------------------------------------------------------
__global__ void k_fin(const float* __restrict__ part, float* __restrict__ out, int n){
  __shared__ float sm[256];
  int b = blockIdx.x, t = threadIdx.x;
  float s = 0.f;
  for (int jj=t; jj<n; jj+=256) s += part[b*1024 + jj];
  sm[t]=s; __syncthreads();
  for (int st=128; st>0; st>>=1){ if (t<st) sm[t]+=sm[t+st]; __syncthreads(); }
  if (t==0) out[b] = sm[0];
}

__global__ __launch_bounds__(256) void k_init_r(float* __restrict__ part){
  __shared__ float sm0[256], sm1[256];
  int t = threadIdx.x;
  float s0=0.f, s1=0.f;
  for (int i=blockIdx.x*256+t; i<VOL; i+=256*256){
    float2 v = make_float2(d_bb[i].x - d_Ap[i].x, d_bb[i].y - d_Ap[i].y);
    d_rr[i]=v; d_pp[i]=v;
    s0 += v.x*v.x; s1 += v.y*v.y;
  }
  sm0[t]=s0; sm1[t]=s1; __syncthreads();
  for (int st=128; st>0; st>>=1){ if (t<st){ sm0[t]+=sm0[t+st]; sm1[t]+=sm1[t+st]; } __syncthreads(); }
  if (t==0){ part[blockIdx.x]=sm0[0]; part[1024+blockIdx.x]=sm1[0]; }
}

__global__ __launch_bounds__(256) void k_update1(float* __restrict__ part){
  __shared__ float sm0[256], sm1[256];
  int t = threadIdx.x;
  float a0 = d_rs[0] / (d_pAp[0] + EPSI);
  float a1 = d_rs[1] / (d_pAp[1] + EPSI);
  float s0=0.f, s1=0.f;
  for (int i=blockIdx.x*256+t; i<VOL; i+=256*256){
    float2 p = d_pp[i], ap = d_Ap[i], xk = d_xk[i], r = d_rr[i];
    xk.x += a0*p.x;  xk.y += a1*p.y;  d_xk[i]=xk;
    r.x  -= a0*ap.x; r.y  -= a1*ap.y; d_rr[i]=r;
    s0 += r.x*r.x;   s1 += r.y*r.y;
  }
  sm0[t]=s0; sm1[t]=s1; __syncthreads();
  for (int st=128; st>0; st>>=1){ if (t<st){ sm0[t]+=sm0[t+st]; sm1[t]+=sm1[t+st]; } __syncthreads(); }
  if (t==0){ part[blockIdx.x]=sm0[0]; part[1024+blockIdx.x]=sm1[0]; }
}

__global__ void k_rscopy(){
  if (threadIdx.x < NB) d_rs[threadIdx.x] = d_rsn[threadIdx.x];
}

__global__ __launch_bounds__(256) void k_unpack(float* __restrict__ out){
  int i = blockIdx.x*256 + threadIdx.x;
  float2 v = d_xk[i];
  out[i] = v.x;
  out[VOL+i] = v.y;
}

// ---------------------------------------------------------------------------
// Host side
// ---------------------------------------------------------------------------
static void applyA(const float2* vin, float2* vout, float* pPart, int beta,
                   float2* pC0, float2* pTmp, const float* pSe, const uchar2* pM8,
                   float2* pR, float2* pP){
  if (beta){
    k_fwdzT<<<dim3(128,4,1), 256>>>(pP, 0, pC0, 1, pR, pP);
    k_rscopy<<<1,32>>>();
  } else {
    k_fwdzT<<<dim3(128,4,1), 256>>>(vin, 0, pC0, 0, 0, 0);
  }
  k_plane1 <<<128, 512, PLANE_SMEM>>>(pC0, pSe, pTmp);
  k_zfuseT <<<dim3(128,4,NR), 256>>>(pTmp, pM8);
  k_plane2 <<<128, 512, PLANE_SMEM>>>(pTmp, pSe, pC0);
  k_invzT_ap<<<dim3(128,4), 256>>>(pC0, vout, beta ? pP : vin, LAMBDA, pPart);
}

extern "C" void kernel_launch(void* const* d_in, const int* in_sizes, int n_in,
                              void* d_out, int out_size){
  const float* x      = (const float*)d_in[0];
  const float* x1     = (const float*)d_in[1];
  const float* x3     = (const float*)d_in[2];
  const float* init_x = (const float*)d_in[3];
  const float* smv    = (const float*)d_in[4];
  float* out = (float*)d_out;

  float2 *pC0, *pTmp, *pB, *pXk, *pR, *pP, *pAp;
  float *pSe, *pRs, *pPAp, *pRsn, *pPart;
  uchar2 *pM8;
  cudaGetSymbolAddress((void**)&pC0,  d_C0);
  cudaGetSymbolAddress((void**)&pTmp, d_tmp);
  cudaGetSymbolAddress((void**)&pSe,  d_Se);
  cudaGetSymbolAddress((void**)&pM8,  d_m8);
  cudaGetSymbolAddress((void**)&pB,   d_bb);
  cudaGetSymbolAddress((void**)&pXk,  d_xk);
  cudaGetSymbolAddress((void**)&pR,   d_rr);
  cudaGetSymbolAddress((void**)&pP,   d_pp);
  cudaGetSymbolAddress((void**)&pAp,  d_Ap);
  cudaGetSymbolAddress((void**)&pRs,  d_rs);
  cudaGetSymbolAddress((void**)&pPAp, d_pAp);
  cudaGetSymbolAddress((void**)&pRsn, d_rsn);
  cudaGetSymbolAddress((void**)&pPart,d_part);

  cudaFuncSetAttribute(k_plane1, cudaFuncAttributeMaxDynamicSharedMemorySize, PLANE_SMEM);
  cudaFuncSetAttribute(k_plane2, cudaFuncAttributeMaxDynamicSharedMemorySize, PLANE_SMEM);

  k_initW <<<1,128>>>();
  k_prep  <<<VOL/256, 256>>>(x, x1, x3, init_x);
  k_prepSe<<<dim3(VOL/256, NR), 256>>>(smv);

  // b = smv_adj( m * (w3*x) ); wx packed is in d_rr
  k_fwdzT  <<<dim3(128,4,NR), 256>>>(pR, pM8, pTmp, 0, 0, 0);
  k_plane2 <<<128, 512, PLANE_SMEM>>>(pTmp, pSe, pC0);
  k_invzT_ap<<<dim3(128,4), 256>>>(pC0, pB, 0, 0.f, 0);

  // r0 = b - A(x0); p = r0; rs = <r0,r0>
  applyA(pXk, pAp, 0, 0, pC0, pTmp, pSe, pM8, pR, pP);
  k_init_r<<<256, 256>>>(pPart);
  k_fin<<<NB, 256>>>(pPart, pRs, 256);

  for (int it=0; it<NITER; ++it){
    applyA(pP, pAp, pPart, (it>0)?1:0, pC0, pTmp, pSe, pM8, pR, pP);
    k_fin<<<NB, 256>>>(pPart, pPAp, 512);
    k_update1<<<256, 256>>>(pPart);
    k_fin<<<NB, 256>>>(pPart, pRsn, 256);
  }

  k_unpack<<<VOL/256, 256>>>(out);
}